// round 10
// baseline (speedup 1.0000x reference)
#include <cuda_runtime.h>
#include <cuda_bf16.h>
#include <cstdint>
#include <cstddef>

// ---------------------------------------------------------------------------
// WindowAttention (Swin-style): B_=4096 windows, N=49, C=384, H=12, hd=32
// Round 10: 3-stage cp.async pipeline in the GEMM (96 KB dynamic SMEM).
//           Attention unchanged.
// ---------------------------------------------------------------------------

#define B_WIN   4096
#define N_TOK   49
#define DIM     384
#define H_HEADS 12
#define HD      32
#define T_TOT   (B_WIN * N_TOK)      // 200704 tokens
#define NW_MASK 64
#define NN      (N_TOK * N_TOK)      // 2401

__device__ float g_qkv[(size_t)T_TOT * 3 * DIM];   // (T, 1152)
__device__ float g_ao [(size_t)T_TOT * DIM];       // (T, 384) tf32-rounded
__device__ float g_xr [(size_t)T_TOT * DIM];       // x, tf32-rounded
__device__ float g_wr [3 * DIM * DIM + DIM * DIM]; // qkv_w | proj_w, rounded
__device__ float g_comb[(size_t)H_HEADS * NW_MASK * NN];  // bias+mask

// ---------------------------------------------------------------------------
// helpers
// ---------------------------------------------------------------------------
__device__ __forceinline__ float to_tf32(float x) {
    asm("cvt.rna.tf32.f32 %0, %0;" : "+f"(x));
    return x;
}

__device__ __forceinline__ void mma_tf32_16x8x8(float d[4], const uint32_t a[4],
                                                const uint32_t b[2]) {
    asm volatile(
        "mma.sync.aligned.m16n8k8.row.col.f32.tf32.tf32.f32 "
        "{%0,%1,%2,%3}, {%4,%5,%6,%7}, {%8,%9}, {%0,%1,%2,%3};\n"
        : "+f"(d[0]), "+f"(d[1]), "+f"(d[2]), "+f"(d[3])
        : "r"(a[0]), "r"(a[1]), "r"(a[2]), "r"(a[3]), "r"(b[0]), "r"(b[1]));
}

__device__ __forceinline__ void ldsm_x4(uint32_t& r0, uint32_t& r1,
                                        uint32_t& r2, uint32_t& r3, uint32_t addr) {
    asm volatile("ldmatrix.sync.aligned.m8n8.x4.shared.b16 {%0,%1,%2,%3}, [%4];\n"
                 : "=r"(r0), "=r"(r1), "=r"(r2), "=r"(r3) : "r"(addr));
}

__device__ __forceinline__ void cp_async16(uint32_t smem_addr, const void* gptr) {
    asm volatile("cp.async.cg.shared.global [%0], [%1], 16;\n"
                 :: "r"(smem_addr), "l"(gptr) : "memory");
}

// ---------------------------------------------------------------------------
// Kernel R: round fp32 -> tf32 (RNA), float4 grid-stride
// ---------------------------------------------------------------------------
__global__ void round_tf32_kernel(const float* __restrict__ src,
                                  float* __restrict__ dst, int n4) {
    int i = blockIdx.x * blockDim.x + threadIdx.x;
    int stride = gridDim.x * blockDim.x;
    for (; i < n4; i += stride) {
        float4 v = ((const float4*)src)[i];
        v.x = to_tf32(v.x); v.y = to_tf32(v.y);
        v.z = to_tf32(v.z); v.w = to_tf32(v.w);
        ((float4*)dst)[i] = v;
    }
}

// ---------------------------------------------------------------------------
// Kernel 0: comb[h][w][n][m] = bias_table[rel_index[n,m]][h] + mask[w][n][m]
// ---------------------------------------------------------------------------
__global__ void comb_kernel(const float* __restrict__ bias_table,
                            const int* __restrict__ rel_index,
                            const float* __restrict__ mask) {
    int idx = blockIdx.x * blockDim.x + threadIdx.x;
    if (idx < H_HEADS * NW_MASK * NN) {
        int h   = idx / (NW_MASK * NN);
        int rem = idx - h * (NW_MASK * NN);
        int w   = rem / NN;
        int nm  = rem - w * NN;
        g_comb[idx] = bias_table[rel_index[nm] * H_HEADS + h] + mask[w * NN + nm];
    }
}

// ---------------------------------------------------------------------------
// Kernel 1/3: pipelined TF32 GEMM  C[m,n] = sum_k A[m,k]*B[n,k] + bias[n]
//   A, B pre-rounded tf32. BM=128, BN=128, BK=32, 256 threads (8 warps 4x2),
//   warp tile 32x64. 3-stage cp.async; XOR-swizzled SMEM; ldmatrix loads.
//   Dynamic SMEM: 96 KB.
// ---------------------------------------------------------------------------
#define GBM 128
#define GBN 128
#define GBK 32
#define GSTAGES 3
#define GEMM_SMEM_BYTES (4 * GSTAGES * (GBM * GBK + GBN * GBK))   // 98304

__global__ __launch_bounds__(256, 2)
void gemm_tf32_pipe(const float* __restrict__ A, const float* __restrict__ B,
                    const float* __restrict__ bias, float* __restrict__ C,
                    int M, int N, int K) {
    extern __shared__ float dynsmem[];
    float* As = dynsmem;                          // [3][GBM*GBK]
    float* Bs = dynsmem + GSTAGES * GBM * GBK;    // [3][GBN*GBK]

    const int tid  = threadIdx.x;
    const int lane = tid & 31;
    const int warp = tid >> 5;
    const int wm   = warp >> 1;         // 0..3 (32 rows each)
    const int wn   = warp & 1;          // 0..1 (64 cols each)
    const int bm   = blockIdx.y * GBM;
    const int bn   = blockIdx.x * GBN;
    const int r4   = lane >> 2;
    const int c4   = lane & 3;

    const uint32_t as_base = (uint32_t)__cvta_generic_to_shared(As);
    const uint32_t bs_base = (uint32_t)__cvta_generic_to_shared(Bs);

    // cp.async loader geometry (A and B tiles both 128x32)
    const int lc4  = tid & 7;
    const int lrow = tid >> 3;
    const int pc4  = lc4 ^ (lrow & 7);

    // ldmatrix lane geometry
    const int l7       = lane & 7;
    const int a_half_m = (lane >> 3) & 1;
    const int a_half_k = lane >> 4;
    const int b_half_k = (lane >> 3) & 1;
    const int b_sel    = lane >> 4;

    int rA7[2]; uint32_t baseA[2];
    #pragma unroll
    for (int mt = 0; mt < 2; mt++) {
        int row = wm * 32 + mt * 16 + a_half_m * 8 + l7;
        rA7[mt]   = row & 7;
        baseA[mt] = (uint32_t)row * 128;
    }
    int rB7[4]; uint32_t baseB[4];
    #pragma unroll
    for (int j = 0; j < 4; j++) {
        int row = wn * 64 + (2 * j + b_sel) * 8 + l7;
        rB7[j]   = row & 7;
        baseB[j] = (uint32_t)row * 128;
    }

    const int kTiles = K / GBK;

    auto issue = [&](int ktf, int s) {
        #pragma unroll
        for (int i = 0; i < 4; i++) {
            int r = lrow + i * 32;
            cp_async16(as_base + (uint32_t)(s * (GBM * GBK) + r * GBK + pc4 * 4) * 4,
                       A + (size_t)(bm + r) * K + ktf + lc4 * 4);
        }
        #pragma unroll
        for (int i = 0; i < 4; i++) {
            int r = lrow + i * 32;
            cp_async16(bs_base + (uint32_t)(s * (GBN * GBK) + r * GBK + pc4 * 4) * 4,
                       B + (size_t)(bn + r) * K + ktf + lc4 * 4);
        }
        asm volatile("cp.async.commit_group;\n" ::: "memory");
    };

    float acc[2][8][4];
    #pragma unroll
    for (int mt = 0; mt < 2; mt++)
        #pragma unroll
        for (int nt = 0; nt < 8; nt++)
            #pragma unroll
            for (int i = 0; i < 4; i++) acc[mt][nt][i] = 0.f;

    // prologue: 2 stages in flight
    issue(0, 0);
    if (kTiles > 1) issue(GBK, 1);

    for (int t = 0; t < kTiles; t++) {
        const int s = t % GSTAGES;
        // issue stage t+2 into the slot consumed at t-1 (safe: barrier below
        // at end of t-1 guaranteed all reads of that slot completed)
        if (t + 2 < kTiles) {
            issue((t + 2) * GBK, (t + 2) % GSTAGES);
            asm volatile("cp.async.wait_group 2;\n" ::: "memory");
        } else if (t + 1 < kTiles) {
            asm volatile("cp.async.wait_group 1;\n" ::: "memory");
        } else {
            asm volatile("cp.async.wait_group 0;\n" ::: "memory");
        }
        __syncthreads();

        const uint32_t asb = as_base + (uint32_t)(s * (GBM * GBK)) * 4;
        const uint32_t bsb = bs_base + (uint32_t)(s * (GBN * GBK)) * 4;
        #pragma unroll
        for (int k8 = 0; k8 < GBK; k8 += 8) {
            const int kk = k8 >> 2;   // 0,2,4,6
            uint32_t af[2][4];
            uint32_t bf[8][2];
            #pragma unroll
            for (int mt = 0; mt < 2; mt++) {
                uint32_t addr = asb + baseA[mt] +
                                (uint32_t)(((kk + a_half_k) ^ rA7[mt]) << 4);
                ldsm_x4(af[mt][0], af[mt][1], af[mt][2], af[mt][3], addr);
            }
            #pragma unroll
            for (int j = 0; j < 4; j++) {
                uint32_t addr = bsb + baseB[j] +
                                (uint32_t)(((kk + b_half_k) ^ rB7[j]) << 4);
                ldsm_x4(bf[2 * j][0], bf[2 * j][1], bf[2 * j + 1][0], bf[2 * j + 1][1], addr);
            }
            #pragma unroll
            for (int mt = 0; mt < 2; mt++)
                #pragma unroll
                for (int nt = 0; nt < 8; nt++)
                    mma_tf32_16x8x8(acc[mt][nt], af[mt], bf[nt]);
        }
        __syncthreads();
    }

    // epilogue: add bias, store fp32
    #pragma unroll
    for (int mt = 0; mt < 2; mt++) {
        int row0 = bm + wm * 32 + mt * 16 + r4;
        #pragma unroll
        for (int nt = 0; nt < 8; nt++) {
            int col = bn + wn * 64 + nt * 8 + 2 * c4;
            float b0 = bias[col], b1 = bias[col + 1];
            float2 v01 = make_float2(acc[mt][nt][0] + b0, acc[mt][nt][1] + b1);
            float2 v23 = make_float2(acc[mt][nt][2] + b0, acc[mt][nt][3] + b1);
            *(float2*)(C + (size_t)row0 * N + col)       = v01;
            *(float2*)(C + (size_t)(row0 + 8) * N + col) = v23;
        }
    }
}

// ---------------------------------------------------------------------------
// Kernel 2: fused attention per (window, head), register-fused softmax
// ---------------------------------------------------------------------------
#define QS_STR 36
#define SS_STR 57

__global__ __launch_bounds__(128)
void attn_fused_kernel() {
    __shared__ float qs[N_TOK][QS_STR];
    __shared__ float ks[N_TOK][QS_STR];
    __shared__ float vt[HD][SS_STR];
    __shared__ float Ss[N_TOK][SS_STR];
    __shared__ float cb[2416];

    const int h    = blockIdx.x;
    const int b    = blockIdx.y;
    const int tid  = threadIdx.x;
    const int lane = tid & 31;
    const int warp = tid >> 5;
    const int r4   = lane >> 2;
    const int c4   = lane & 3;
    const float scale = 0.1767766952966369f;

    for (int i = tid; i < N_TOK * 8; i += 128) { int r = i >> 3; Ss[r][49 + (i & 7)] = 0.f; }
    for (int i = tid; i < HD * 8;    i += 128) { int r = i >> 3; vt[r][49 + (i & 7)] = 0.f; }

    const float* base = g_qkv + (size_t)b * N_TOK * (3 * DIM) + h * HD;
    #pragma unroll 4
    for (int idx = tid; idx < N_TOK * HD; idx += 128) {
        int n = idx >> 5;
        int d = idx & 31;
        const float* rp = base + (size_t)n * (3 * DIM) + d;
        qs[n][d] = to_tf32(rp[0] * scale);
        ks[n][d] = to_tf32(rp[DIM]);
        vt[d][n] = to_tf32(rp[2 * DIM]);
    }
    const float* cbg = g_comb + (size_t)(h * NW_MASK + (b & (NW_MASK - 1))) * NN;
    for (int i = tid; i < NN; i += 128) cb[i] = cbg[i];
    __syncthreads();

    {
        float acc[7][4];
        #pragma unroll
        for (int nt = 0; nt < 7; nt++)
            #pragma unroll
            for (int i = 0; i < 4; i++) acc[nt][i] = 0.f;

        const int am  = warp * 16;
        const int ar0 = min(am + r4, N_TOK - 1);
        const int ar1 = min(am + r4 + 8, N_TOK - 1);
        #pragma unroll
        for (int k8 = 0; k8 < 32; k8 += 8) {
            uint32_t af[4], bf[7][2];
            af[0] = __float_as_uint(qs[ar0][k8 + c4    ]);
            af[1] = __float_as_uint(qs[ar1][k8 + c4    ]);
            af[2] = __float_as_uint(qs[ar0][k8 + c4 + 4]);
            af[3] = __float_as_uint(qs[ar1][k8 + c4 + 4]);
            #pragma unroll
            for (int nt = 0; nt < 7; nt++) {
                int br = min(nt * 8 + r4, N_TOK - 1);
                bf[nt][0] = __float_as_uint(ks[br][k8 + c4    ]);
                bf[nt][1] = __float_as_uint(ks[br][k8 + c4 + 4]);
            }
            #pragma unroll
            for (int nt = 0; nt < 7; nt++)
                mma_tf32_16x8x8(acc[nt], af, bf[nt]);
        }

        const int n0  = am + r4;
        const int n1  = n0 + 8;
        const int cr0 = min(n0, N_TOK - 1) * N_TOK;
        const int cr1 = min(n1, N_TOK - 1) * N_TOK;
        float s0 = 0.f, s1 = 0.f;
        #pragma unroll
        for (int nt = 0; nt < 7; nt++) {
            int col0 = nt * 8 + 2 * c4;
            int col1 = col0 + 1;
            float e00 = (col0 < N_TOK) ? __expf(acc[nt][0] + cb[cr0 + col0]) : 0.f;
            float e01 = (col1 < N_TOK) ? __expf(acc[nt][1] + cb[cr0 + col1]) : 0.f;
            float e10 = (col0 < N_TOK) ? __expf(acc[nt][2] + cb[cr1 + col0]) : 0.f;
            float e11 = (col1 < N_TOK) ? __expf(acc[nt][3] + cb[cr1 + col1]) : 0.f;
            acc[nt][0] = e00; acc[nt][1] = e01; acc[nt][2] = e10; acc[nt][3] = e11;
            s0 += e00 + e01;
            s1 += e10 + e11;
        }
        s0 += __shfl_xor_sync(0xffffffffu, s0, 1);
        s0 += __shfl_xor_sync(0xffffffffu, s0, 2);
        s1 += __shfl_xor_sync(0xffffffffu, s1, 1);
        s1 += __shfl_xor_sync(0xffffffffu, s1, 2);
        float inv0 = __frcp_rn(s0);
        float inv1 = __frcp_rn(s1);

        #pragma unroll
        for (int nt = 0; nt < 7; nt++) {
            int col0 = nt * 8 + 2 * c4;
            int col1 = col0 + 1;
            if (n0 < N_TOK && col0 < N_TOK) Ss[n0][col0] = to_tf32(acc[nt][0] * inv0);
            if (n0 < N_TOK && col1 < N_TOK) Ss[n0][col1] = to_tf32(acc[nt][1] * inv0);
            if (n1 < N_TOK && col0 < N_TOK) Ss[n1][col0] = to_tf32(acc[nt][2] * inv1);
            if (n1 < N_TOK && col1 < N_TOK) Ss[n1][col1] = to_tf32(acc[nt][3] * inv1);
        }
    }
    __syncthreads();

    {
        float acc[4][4];
        #pragma unroll
        for (int nt = 0; nt < 4; nt++)
            #pragma unroll
            for (int i = 0; i < 4; i++) acc[nt][i] = 0.f;

        const int am  = warp * 16;
        const int ar0 = min(am + r4, N_TOK - 1);
        const int ar1 = min(am + r4 + 8, N_TOK - 1);
        #pragma unroll
        for (int k8 = 0; k8 < 56; k8 += 8) {
            uint32_t af[4], bf[4][2];
            af[0] = __float_as_uint(Ss[ar0][k8 + c4    ]);
            af[1] = __float_as_uint(Ss[ar1][k8 + c4    ]);
            af[2] = __float_as_uint(Ss[ar0][k8 + c4 + 4]);
            af[3] = __float_as_uint(Ss[ar1][k8 + c4 + 4]);
            #pragma unroll
            for (int nt = 0; nt < 4; nt++) {
                bf[nt][0] = __float_as_uint(vt[nt * 8 + r4][k8 + c4    ]);
                bf[nt][1] = __float_as_uint(vt[nt * 8 + r4][k8 + c4 + 4]);
            }
            #pragma unroll
            for (int nt = 0; nt < 4; nt++)
                mma_tf32_16x8x8(acc[nt], af, bf[nt]);
        }
        float* aob = g_ao + (size_t)b * N_TOK * DIM + h * HD;
        const int n0 = am + r4, n1 = n0 + 8;
        #pragma unroll
        for (int nt = 0; nt < 4; nt++) {
            int col = nt * 8 + 2 * c4;
            if (n0 < N_TOK)
                *(float2*)(aob + (size_t)n0 * DIM + col) =
                    make_float2(to_tf32(acc[nt][0]), to_tf32(acc[nt][1]));
            if (n1 < N_TOK)
                *(float2*)(aob + (size_t)n1 * DIM + col) =
                    make_float2(to_tf32(acc[nt][2]), to_tf32(acc[nt][3]));
        }
    }
}

// ---------------------------------------------------------------------------
// launch
// ---------------------------------------------------------------------------
extern "C" void kernel_launch(void* const* d_in, const int* in_sizes, int n_in,
                              void* d_out, int out_size) {
    const float* x          = (const float*)d_in[0];
    const float* mask       = (const float*)d_in[1];
    const float* qkv_w      = (const float*)d_in[2];
    const float* qkv_b      = (const float*)d_in[3];
    const float* proj_w     = (const float*)d_in[4];
    const float* proj_b     = (const float*)d_in[5];
    const float* bias_table = (const float*)d_in[6];
    const int*   rel_index  = (const int*)d_in[7];
    float* out = (float*)d_out;

    void* p_qkv = nullptr; void* p_ao = nullptr;
    void* p_xr  = nullptr; void* p_wr = nullptr;
    cudaGetSymbolAddress(&p_qkv, g_qkv);
    cudaGetSymbolAddress(&p_ao,  g_ao);
    cudaGetSymbolAddress(&p_xr,  g_xr);
    cudaGetSymbolAddress(&p_wr,  g_wr);
    float* qkv = (float*)p_qkv;
    float* ao  = (float*)p_ao;
    float* xr  = (float*)p_xr;
    float* qkvw_r = (float*)p_wr;
    float* projw_r = qkvw_r + 3 * DIM * DIM;

    cudaFuncSetAttribute(gemm_tf32_pipe,
                         cudaFuncAttributeMaxDynamicSharedMemorySize,
                         GEMM_SMEM_BYTES);

    round_tf32_kernel<<<2048, 256>>>(x, xr, (T_TOT * DIM) / 4);
    round_tf32_kernel<<<256, 256>>>(qkv_w, qkvw_r, (3 * DIM * DIM) / 4);
    round_tf32_kernel<<<256, 256>>>(proj_w, projw_r, (DIM * DIM) / 4);
    {
        int n = H_HEADS * NW_MASK * NN;
        comb_kernel<<<(n + 255) / 256, 256>>>(bias_table, rel_index, mask);
    }
    // 1) QKV GEMM: (T,384) @ (1152,384)^T -> (T,1152)
    {
        dim3 grid((3 * DIM) / GBN, T_TOT / GBM);
        gemm_tf32_pipe<<<grid, 256, GEMM_SMEM_BYTES>>>(xr, qkvw_r, qkv_b, qkv,
                                                       T_TOT, 3 * DIM, DIM);
    }
    // 2) fused attention
    {
        dim3 grid(H_HEADS, B_WIN);
        attn_fused_kernel<<<grid, 128>>>();
    }
    // 3) proj GEMM: (T,384) @ (384,384)^T -> (T,384)
    {
        dim3 grid(DIM / GBN, T_TOT / GBM);
        gemm_tf32_pipe<<<grid, 256, GEMM_SMEM_BYTES>>>(ao, projw_r, proj_b, out,
                                                       T_TOT, DIM, DIM);
    }
}

// round 11
// speedup vs baseline: 1.0717x; 1.0717x over previous
#include <cuda_runtime.h>
#include <cuda_bf16.h>
#include <cstdint>
#include <cstddef>

// ---------------------------------------------------------------------------
// WindowAttention (Swin-style): B_=4096 windows, N=49, C=384, H=12, hd=32
// Round 11: revert GEMM to 2-stage (R9); attention processes 2 windows/CTA
//           (b and b+2048 share the comb tile), 256 threads, dynamic SMEM.
// ---------------------------------------------------------------------------

#define B_WIN   4096
#define N_TOK   49
#define DIM     384
#define H_HEADS 12
#define HD      32
#define T_TOT   (B_WIN * N_TOK)      // 200704 tokens
#define NW_MASK 64
#define NN      (N_TOK * N_TOK)      // 2401

__device__ float g_qkv[(size_t)T_TOT * 3 * DIM];   // (T, 1152)
__device__ float g_ao [(size_t)T_TOT * DIM];       // (T, 384) tf32-rounded
__device__ float g_xr [(size_t)T_TOT * DIM];       // x, tf32-rounded
__device__ float g_wr [3 * DIM * DIM + DIM * DIM]; // qkv_w | proj_w, rounded
__device__ float g_comb[(size_t)H_HEADS * NW_MASK * NN];  // bias+mask

// ---------------------------------------------------------------------------
// helpers
// ---------------------------------------------------------------------------
__device__ __forceinline__ float to_tf32(float x) {
    asm("cvt.rna.tf32.f32 %0, %0;" : "+f"(x));
    return x;
}

__device__ __forceinline__ void mma_tf32_16x8x8(float d[4], const uint32_t a[4],
                                                const uint32_t b[2]) {
    asm volatile(
        "mma.sync.aligned.m16n8k8.row.col.f32.tf32.tf32.f32 "
        "{%0,%1,%2,%3}, {%4,%5,%6,%7}, {%8,%9}, {%0,%1,%2,%3};\n"
        : "+f"(d[0]), "+f"(d[1]), "+f"(d[2]), "+f"(d[3])
        : "r"(a[0]), "r"(a[1]), "r"(a[2]), "r"(a[3]), "r"(b[0]), "r"(b[1]));
}

__device__ __forceinline__ void ldsm_x4(uint32_t& r0, uint32_t& r1,
                                        uint32_t& r2, uint32_t& r3, uint32_t addr) {
    asm volatile("ldmatrix.sync.aligned.m8n8.x4.shared.b16 {%0,%1,%2,%3}, [%4];\n"
                 : "=r"(r0), "=r"(r1), "=r"(r2), "=r"(r3) : "r"(addr));
}

__device__ __forceinline__ void cp_async16(uint32_t smem_addr, const void* gptr) {
    asm volatile("cp.async.cg.shared.global [%0], [%1], 16;\n"
                 :: "r"(smem_addr), "l"(gptr) : "memory");
}

// ---------------------------------------------------------------------------
// Kernel R: round fp32 -> tf32 (RNA), float4 grid-stride
// ---------------------------------------------------------------------------
__global__ void round_tf32_kernel(const float* __restrict__ src,
                                  float* __restrict__ dst, int n4) {
    int i = blockIdx.x * blockDim.x + threadIdx.x;
    int stride = gridDim.x * blockDim.x;
    for (; i < n4; i += stride) {
        float4 v = ((const float4*)src)[i];
        v.x = to_tf32(v.x); v.y = to_tf32(v.y);
        v.z = to_tf32(v.z); v.w = to_tf32(v.w);
        ((float4*)dst)[i] = v;
    }
}

// ---------------------------------------------------------------------------
// Kernel 0: comb[h][w][n][m] = bias_table[rel_index[n,m]][h] + mask[w][n][m]
// ---------------------------------------------------------------------------
__global__ void comb_kernel(const float* __restrict__ bias_table,
                            const int* __restrict__ rel_index,
                            const float* __restrict__ mask) {
    int idx = blockIdx.x * blockDim.x + threadIdx.x;
    if (idx < H_HEADS * NW_MASK * NN) {
        int h   = idx / (NW_MASK * NN);
        int rem = idx - h * (NW_MASK * NN);
        int w   = rem / NN;
        int nm  = rem - w * NN;
        g_comb[idx] = bias_table[rel_index[nm] * H_HEADS + h] + mask[w * NN + nm];
    }
}

// ---------------------------------------------------------------------------
// Kernel 1/3: pipelined TF32 GEMM (R9 config: 2-stage, BM=BN=128, BK=32)
// ---------------------------------------------------------------------------
#define GBM 128
#define GBN 128
#define GBK 32
#define GEMM_SMEM_BYTES (4 * (2 * GBM * GBK + 2 * GBN * GBK))   // 65536

__global__ __launch_bounds__(256, 2)
void gemm_tf32_pipe(const float* __restrict__ A, const float* __restrict__ B,
                    const float* __restrict__ bias, float* __restrict__ C,
                    int M, int N, int K) {
    extern __shared__ float dynsmem[];
    float* As = dynsmem;                    // [2][GBM*GBK]
    float* Bs = dynsmem + 2 * GBM * GBK;    // [2][GBN*GBK]

    const int tid  = threadIdx.x;
    const int lane = tid & 31;
    const int warp = tid >> 5;
    const int wm   = warp >> 1;
    const int wn   = warp & 1;
    const int bm   = blockIdx.y * GBM;
    const int bn   = blockIdx.x * GBN;
    const int r4   = lane >> 2;
    const int c4   = lane & 3;

    const uint32_t as_base = (uint32_t)__cvta_generic_to_shared(As);
    const uint32_t bs_base = (uint32_t)__cvta_generic_to_shared(Bs);

    const int lc4  = tid & 7;
    const int lrow = tid >> 3;
    const int pc4  = lc4 ^ (lrow & 7);

    const int l7       = lane & 7;
    const int a_half_m = (lane >> 3) & 1;
    const int a_half_k = lane >> 4;
    const int b_half_k = (lane >> 3) & 1;
    const int b_sel    = lane >> 4;

    int rA7[2]; uint32_t baseA[2];
    #pragma unroll
    for (int mt = 0; mt < 2; mt++) {
        int row = wm * 32 + mt * 16 + a_half_m * 8 + l7;
        rA7[mt]   = row & 7;
        baseA[mt] = (uint32_t)row * 128;
    }
    int rB7[4]; uint32_t baseB[4];
    #pragma unroll
    for (int j = 0; j < 4; j++) {
        int row = wn * 64 + (2 * j + b_sel) * 8 + l7;
        rB7[j]   = row & 7;
        baseB[j] = (uint32_t)row * 128;
    }

    const int kTiles = K / GBK;

    auto issue = [&](int ktf, int s) {
        #pragma unroll
        for (int i = 0; i < 4; i++) {
            int r = lrow + i * 32;
            cp_async16(as_base + (uint32_t)(s * (GBM * GBK) + r * GBK + pc4 * 4) * 4,
                       A + (size_t)(bm + r) * K + ktf + lc4 * 4);
        }
        #pragma unroll
        for (int i = 0; i < 4; i++) {
            int r = lrow + i * 32;
            cp_async16(bs_base + (uint32_t)(s * (GBN * GBK) + r * GBK + pc4 * 4) * 4,
                       B + (size_t)(bn + r) * K + ktf + lc4 * 4);
        }
        asm volatile("cp.async.commit_group;\n" ::: "memory");
    };

    float acc[2][8][4];
    #pragma unroll
    for (int mt = 0; mt < 2; mt++)
        #pragma unroll
        for (int nt = 0; nt < 8; nt++)
            #pragma unroll
            for (int i = 0; i < 4; i++) acc[mt][nt][i] = 0.f;

    issue(0, 0);

    for (int t = 0; t < kTiles; t++) {
        const int s = t & 1;
        if (t + 1 < kTiles) {
            issue((t + 1) * GBK, s ^ 1);
            asm volatile("cp.async.wait_group 1;\n" ::: "memory");
        } else {
            asm volatile("cp.async.wait_group 0;\n" ::: "memory");
        }
        __syncthreads();

        const uint32_t asb = as_base + (uint32_t)(s * (GBM * GBK)) * 4;
        const uint32_t bsb = bs_base + (uint32_t)(s * (GBN * GBK)) * 4;
        #pragma unroll
        for (int k8 = 0; k8 < GBK; k8 += 8) {
            const int kk = k8 >> 2;
            uint32_t af[2][4];
            uint32_t bf[8][2];
            #pragma unroll
            for (int mt = 0; mt < 2; mt++) {
                uint32_t addr = asb + baseA[mt] +
                                (uint32_t)(((kk + a_half_k) ^ rA7[mt]) << 4);
                ldsm_x4(af[mt][0], af[mt][1], af[mt][2], af[mt][3], addr);
            }
            #pragma unroll
            for (int j = 0; j < 4; j++) {
                uint32_t addr = bsb + baseB[j] +
                                (uint32_t)(((kk + b_half_k) ^ rB7[j]) << 4);
                ldsm_x4(bf[2 * j][0], bf[2 * j][1], bf[2 * j + 1][0], bf[2 * j + 1][1], addr);
            }
            #pragma unroll
            for (int mt = 0; mt < 2; mt++)
                #pragma unroll
                for (int nt = 0; nt < 8; nt++)
                    mma_tf32_16x8x8(acc[mt][nt], af[mt], bf[nt]);
        }
        __syncthreads();
    }

    #pragma unroll
    for (int mt = 0; mt < 2; mt++) {
        int row0 = bm + wm * 32 + mt * 16 + r4;
        #pragma unroll
        for (int nt = 0; nt < 8; nt++) {
            int col = bn + wn * 64 + nt * 8 + 2 * c4;
            float b0 = bias[col], b1 = bias[col + 1];
            float2 v01 = make_float2(acc[mt][nt][0] + b0, acc[mt][nt][1] + b1);
            float2 v23 = make_float2(acc[mt][nt][2] + b0, acc[mt][nt][3] + b1);
            *(float2*)(C + (size_t)row0 * N + col)       = v01;
            *(float2*)(C + (size_t)(row0 + 8) * N + col) = v23;
        }
    }
}

// ---------------------------------------------------------------------------
// Kernel 2: fused attention, 2 windows per CTA (b and b+2048 share comb tile)
//   grid (H=12, 64, 32), 256 threads (8 warps; warps 0-3 -> win 0, 4-7 -> win 1)
//   dynamic SMEM ~75 KB
// ---------------------------------------------------------------------------
#define QS_STR 36
#define SS_STR 57
// floats: qs 2*49*36, ks 2*49*36, vt 2*32*57, Ss 2*49*57, cb 2416
#define ATTN_F_QS  (2 * N_TOK * QS_STR)
#define ATTN_F_VT  (2 * HD * SS_STR)
#define ATTN_F_SS  (2 * N_TOK * SS_STR)
#define ATTN_SMEM_FLOATS (2 * ATTN_F_QS + ATTN_F_VT + ATTN_F_SS + 2416)
#define ATTN_SMEM_BYTES  (4 * ATTN_SMEM_FLOATS)   // 74824

__global__ __launch_bounds__(256)
void attn_fused2_kernel() {
    extern __shared__ float sm[];
    float* cb = sm + 2 * ATTN_F_QS + ATTN_F_VT + ATTN_F_SS;

    const int h    = blockIdx.x;
    const int tid  = threadIdx.x;
    const int wg   = tid >> 7;          // window slot 0/1
    const int tl   = tid & 127;         // local tid within window group
    const int lane = tid & 31;
    const int warp = (tid >> 5) & 3;    // local warp within window group
    const int r4   = lane >> 2;
    const int c4   = lane & 3;
    const float scale = 0.1767766952966369f;

    const int b = blockIdx.y + NW_MASK * (blockIdx.z + wg * 32);

    float* qsw = sm + wg * (N_TOK * QS_STR);
    float* ksw = sm + ATTN_F_QS + wg * (N_TOK * QS_STR);
    float* vtw = sm + 2 * ATTN_F_QS + wg * (HD * SS_STR);
    float* Ssw = sm + 2 * ATTN_F_QS + ATTN_F_VT + wg * (N_TOK * SS_STR);

    // zero pad columns (49..56) of Ss and vt for this window
    for (int i = tl; i < N_TOK * 8; i += 128) { int r = i >> 3; Ssw[r * SS_STR + 49 + (i & 7)] = 0.f; }
    for (int i = tl; i < HD * 8;    i += 128) { int r = i >> 3; vtw[r * SS_STR + 49 + (i & 7)] = 0.f; }

    // load q,k,v for this window (q pre-scaled, tf32-rounded); v transposed
    const float* base = g_qkv + (size_t)b * N_TOK * (3 * DIM) + h * HD;
    #pragma unroll 4
    for (int idx = tl; idx < N_TOK * HD; idx += 128) {
        int n = idx >> 5;
        int d = idx & 31;
        const float* rp = base + (size_t)n * (3 * DIM) + d;
        qsw[n * QS_STR + d] = to_tf32(rp[0] * scale);
        ksw[n * QS_STR + d] = to_tf32(rp[DIM]);
        vtw[d * SS_STR + n] = to_tf32(rp[2 * DIM]);
    }
    // stage comb (shared by both windows): (h, blockIdx.y)
    const float* cbg = g_comb + (size_t)(h * NW_MASK + blockIdx.y) * NN;
    for (int i = tid; i < NN; i += 256) cb[i] = cbg[i];
    __syncthreads();

    // --- S = (q*scale) @ k^T via mma; softmax fused in registers ---
    {
        float acc[7][4];
        #pragma unroll
        for (int nt = 0; nt < 7; nt++)
            #pragma unroll
            for (int i = 0; i < 4; i++) acc[nt][i] = 0.f;

        const int am  = warp * 16;
        const int ar0 = min(am + r4, N_TOK - 1);
        const int ar1 = min(am + r4 + 8, N_TOK - 1);
        #pragma unroll
        for (int k8 = 0; k8 < 32; k8 += 8) {
            uint32_t af[4], bf[7][2];
            af[0] = __float_as_uint(qsw[ar0 * QS_STR + k8 + c4    ]);
            af[1] = __float_as_uint(qsw[ar1 * QS_STR + k8 + c4    ]);
            af[2] = __float_as_uint(qsw[ar0 * QS_STR + k8 + c4 + 4]);
            af[3] = __float_as_uint(qsw[ar1 * QS_STR + k8 + c4 + 4]);
            #pragma unroll
            for (int nt = 0; nt < 7; nt++) {
                int br = min(nt * 8 + r4, N_TOK - 1);
                bf[nt][0] = __float_as_uint(ksw[br * QS_STR + k8 + c4    ]);
                bf[nt][1] = __float_as_uint(ksw[br * QS_STR + k8 + c4 + 4]);
            }
            #pragma unroll
            for (int nt = 0; nt < 7; nt++)
                mma_tf32_16x8x8(acc[nt], af, bf[nt]);
        }

        const int n0  = am + r4;
        const int n1  = n0 + 8;
        const int cr0 = min(n0, N_TOK - 1) * N_TOK;
        const int cr1 = min(n1, N_TOK - 1) * N_TOK;
        float s0 = 0.f, s1 = 0.f;
        #pragma unroll
        for (int nt = 0; nt < 7; nt++) {
            int col0 = nt * 8 + 2 * c4;
            int col1 = col0 + 1;
            float e00 = (col0 < N_TOK) ? __expf(acc[nt][0] + cb[cr0 + col0]) : 0.f;
            float e01 = (col1 < N_TOK) ? __expf(acc[nt][1] + cb[cr0 + col1]) : 0.f;
            float e10 = (col0 < N_TOK) ? __expf(acc[nt][2] + cb[cr1 + col0]) : 0.f;
            float e11 = (col1 < N_TOK) ? __expf(acc[nt][3] + cb[cr1 + col1]) : 0.f;
            acc[nt][0] = e00; acc[nt][1] = e01; acc[nt][2] = e10; acc[nt][3] = e11;
            s0 += e00 + e01;
            s1 += e10 + e11;
        }
        s0 += __shfl_xor_sync(0xffffffffu, s0, 1);
        s0 += __shfl_xor_sync(0xffffffffu, s0, 2);
        s1 += __shfl_xor_sync(0xffffffffu, s1, 1);
        s1 += __shfl_xor_sync(0xffffffffu, s1, 2);
        float inv0 = __frcp_rn(s0);
        float inv1 = __frcp_rn(s1);

        #pragma unroll
        for (int nt = 0; nt < 7; nt++) {
            int col0 = nt * 8 + 2 * c4;
            int col1 = col0 + 1;
            if (n0 < N_TOK && col0 < N_TOK) Ssw[n0 * SS_STR + col0] = to_tf32(acc[nt][0] * inv0);
            if (n0 < N_TOK && col1 < N_TOK) Ssw[n0 * SS_STR + col1] = to_tf32(acc[nt][1] * inv0);
            if (n1 < N_TOK && col0 < N_TOK) Ssw[n1 * SS_STR + col0] = to_tf32(acc[nt][2] * inv1);
            if (n1 < N_TOK && col1 < N_TOK) Ssw[n1 * SS_STR + col1] = to_tf32(acc[nt][3] * inv1);
        }
    }
    __syncthreads();

    // --- O = P @ V via mma; store tf32-rounded ---
    {
        float acc[4][4];
        #pragma unroll
        for (int nt = 0; nt < 4; nt++)
            #pragma unroll
            for (int i = 0; i < 4; i++) acc[nt][i] = 0.f;

        const int am  = warp * 16;
        const int ar0 = min(am + r4, N_TOK - 1);
        const int ar1 = min(am + r4 + 8, N_TOK - 1);
        #pragma unroll
        for (int k8 = 0; k8 < 56; k8 += 8) {
            uint32_t af[4], bf[4][2];
            af[0] = __float_as_uint(Ssw[ar0 * SS_STR + k8 + c4    ]);
            af[1] = __float_as_uint(Ssw[ar1 * SS_STR + k8 + c4    ]);
            af[2] = __float_as_uint(Ssw[ar0 * SS_STR + k8 + c4 + 4]);
            af[3] = __float_as_uint(Ssw[ar1 * SS_STR + k8 + c4 + 4]);
            #pragma unroll
            for (int nt = 0; nt < 4; nt++) {
                bf[nt][0] = __float_as_uint(vtw[(nt * 8 + r4) * SS_STR + k8 + c4    ]);
                bf[nt][1] = __float_as_uint(vtw[(nt * 8 + r4) * SS_STR + k8 + c4 + 4]);
            }
            #pragma unroll
            for (int nt = 0; nt < 4; nt++)
                mma_tf32_16x8x8(acc[nt], af, bf[nt]);
        }
        float* aob = g_ao + (size_t)b * N_TOK * DIM + h * HD;
        const int n0 = am + r4, n1 = n0 + 8;
        #pragma unroll
        for (int nt = 0; nt < 4; nt++) {
            int col = nt * 8 + 2 * c4;
            if (n0 < N_TOK)
                *(float2*)(aob + (size_t)n0 * DIM + col) =
                    make_float2(to_tf32(acc[nt][0]), to_tf32(acc[nt][1]));
            if (n1 < N_TOK)
                *(float2*)(aob + (size_t)n1 * DIM + col) =
                    make_float2(to_tf32(acc[nt][2]), to_tf32(acc[nt][3]));
        }
    }
}

// ---------------------------------------------------------------------------
// launch
// ---------------------------------------------------------------------------
extern "C" void kernel_launch(void* const* d_in, const int* in_sizes, int n_in,
                              void* d_out, int out_size) {
    const float* x          = (const float*)d_in[0];
    const float* mask       = (const float*)d_in[1];
    const float* qkv_w      = (const float*)d_in[2];
    const float* qkv_b      = (const float*)d_in[3];
    const float* proj_w     = (const float*)d_in[4];
    const float* proj_b     = (const float*)d_in[5];
    const float* bias_table = (const float*)d_in[6];
    const int*   rel_index  = (const int*)d_in[7];
    float* out = (float*)d_out;

    void* p_qkv = nullptr; void* p_ao = nullptr;
    void* p_xr  = nullptr; void* p_wr = nullptr;
    cudaGetSymbolAddress(&p_qkv, g_qkv);
    cudaGetSymbolAddress(&p_ao,  g_ao);
    cudaGetSymbolAddress(&p_xr,  g_xr);
    cudaGetSymbolAddress(&p_wr,  g_wr);
    float* qkv = (float*)p_qkv;
    float* ao  = (float*)p_ao;
    float* xr  = (float*)p_xr;
    float* qkvw_r = (float*)p_wr;
    float* projw_r = qkvw_r + 3 * DIM * DIM;

    cudaFuncSetAttribute(gemm_tf32_pipe,
                         cudaFuncAttributeMaxDynamicSharedMemorySize,
                         GEMM_SMEM_BYTES);
    cudaFuncSetAttribute(attn_fused2_kernel,
                         cudaFuncAttributeMaxDynamicSharedMemorySize,
                         ATTN_SMEM_BYTES);

    round_tf32_kernel<<<2048, 256>>>(x, xr, (T_TOT * DIM) / 4);
    round_tf32_kernel<<<256, 256>>>(qkv_w, qkvw_r, (3 * DIM * DIM) / 4);
    round_tf32_kernel<<<256, 256>>>(proj_w, projw_r, (DIM * DIM) / 4);
    {
        int n = H_HEADS * NW_MASK * NN;
        comb_kernel<<<(n + 255) / 256, 256>>>(bias_table, rel_index, mask);
    }
    // 1) QKV GEMM: (T,384) @ (1152,384)^T -> (T,1152)
    {
        dim3 grid((3 * DIM) / GBN, T_TOT / GBM);
        gemm_tf32_pipe<<<grid, 256, GEMM_SMEM_BYTES>>>(xr, qkvw_r, qkv_b, qkv,
                                                       T_TOT, 3 * DIM, DIM);
    }
    // 2) fused attention: 2 windows per CTA
    {
        dim3 grid(H_HEADS, NW_MASK, B_WIN / NW_MASK / 2);
        attn_fused2_kernel<<<grid, 256, ATTN_SMEM_BYTES>>>();
    }
    // 3) proj GEMM: (T,384) @ (384,384)^T -> (T,384)
    {
        dim3 grid(DIM / GBN, T_TOT / GBM);
        gemm_tf32_pipe<<<grid, 256, GEMM_SMEM_BYTES>>>(ao, projw_r, proj_b, out,
                                                       T_TOT, DIM, DIM);
    }
}

// round 13
// speedup vs baseline: 1.4607x; 1.3629x over previous
#include <cuda_runtime.h>
#include <cuda_bf16.h>
#include <cuda_fp16.h>
#include <cstdint>
#include <cstddef>

// ---------------------------------------------------------------------------
// WindowAttention (Swin-style): B_=4096 windows, N=49, C=384, H=12, hd=32
// Round 13: GEMMs on fp16 mma.sync m16n8k16 (2x tf32 throughput, same
//           10-bit mantissa). Attention internals unchanged (tf32 mma);
//           ao stored fp16. tcgen05 abandoned (ptxas targets sm_103 plain).
// ---------------------------------------------------------------------------

#define B_WIN   4096
#define N_TOK   49
#define DIM     384
#define H_HEADS 12
#define HD      32
#define T_TOT   (B_WIN * N_TOK)      // 200704 tokens
#define NW_MASK 64
#define NN      (N_TOK * N_TOK)      // 2401

__device__ float  g_qkv[(size_t)T_TOT * 3 * DIM];   // (T, 1152) fp32
__device__ __half g_aoh[(size_t)T_TOT * DIM];       // (T, 384) fp16
__device__ __half g_xh [(size_t)T_TOT * DIM];       // x, fp16
__device__ __half g_wh [3 * DIM * DIM + DIM * DIM]; // qkv_w | proj_w fp16
__device__ float  g_comb[(size_t)H_HEADS * NW_MASK * NN];  // bias+mask

// ---------------------------------------------------------------------------
// helpers
// ---------------------------------------------------------------------------
__device__ __forceinline__ float to_tf32(float x) {
    asm("cvt.rna.tf32.f32 %0, %0;" : "+f"(x));
    return x;
}

__device__ __forceinline__ void mma_tf32_16x8x8(float d[4], const uint32_t a[4],
                                                const uint32_t b[2]) {
    asm volatile(
        "mma.sync.aligned.m16n8k8.row.col.f32.tf32.tf32.f32 "
        "{%0,%1,%2,%3}, {%4,%5,%6,%7}, {%8,%9}, {%0,%1,%2,%3};\n"
        : "+f"(d[0]), "+f"(d[1]), "+f"(d[2]), "+f"(d[3])
        : "r"(a[0]), "r"(a[1]), "r"(a[2]), "r"(a[3]), "r"(b[0]), "r"(b[1]));
}

__device__ __forceinline__ void mma_f16_16x8x16(float d[4], const uint32_t a[4],
                                                const uint32_t b[2]) {
    asm volatile(
        "mma.sync.aligned.m16n8k16.row.col.f32.f16.f16.f32 "
        "{%0,%1,%2,%3}, {%4,%5,%6,%7}, {%8,%9}, {%0,%1,%2,%3};\n"
        : "+f"(d[0]), "+f"(d[1]), "+f"(d[2]), "+f"(d[3])
        : "r"(a[0]), "r"(a[1]), "r"(a[2]), "r"(a[3]), "r"(b[0]), "r"(b[1]));
}

__device__ __forceinline__ void ldsm_x4(uint32_t& r0, uint32_t& r1,
                                        uint32_t& r2, uint32_t& r3, uint32_t addr) {
    asm volatile("ldmatrix.sync.aligned.m8n8.x4.shared.b16 {%0,%1,%2,%3}, [%4];\n"
                 : "=r"(r0), "=r"(r1), "=r"(r2), "=r"(r3) : "r"(addr));
}

__device__ __forceinline__ void cp_async16(uint32_t smem_addr, const void* gptr) {
    asm volatile("cp.async.cg.shared.global [%0], [%1], 16;\n"
                 :: "r"(smem_addr), "l"(gptr) : "memory");
}

// ---------------------------------------------------------------------------
// Kernel R: convert fp32 -> fp16 (RN), 4 floats per thread-step
// ---------------------------------------------------------------------------
__global__ void f32_to_f16_kernel(const float* __restrict__ src,
                                  __half* __restrict__ dst, int n4) {
    int i = blockIdx.x * blockDim.x + threadIdx.x;
    int stride = gridDim.x * blockDim.x;
    for (; i < n4; i += stride) {
        float4 v = ((const float4*)src)[i];
        __half2 h01 = __floats2half2_rn(v.x, v.y);
        __half2 h23 = __floats2half2_rn(v.z, v.w);
        uint2 o;
        o.x = *(uint32_t*)&h01;
        o.y = *(uint32_t*)&h23;
        ((uint2*)dst)[i] = o;
    }
}

// ---------------------------------------------------------------------------
// Kernel 0: comb[h][w][n][m] = bias_table[rel_index[n,m]][h] + mask[w][n][m]
// ---------------------------------------------------------------------------
__global__ void comb_kernel(const float* __restrict__ bias_table,
                            const int* __restrict__ rel_index,
                            const float* __restrict__ mask) {
    int idx = blockIdx.x * blockDim.x + threadIdx.x;
    if (idx < H_HEADS * NW_MASK * NN) {
        int h   = idx / (NW_MASK * NN);
        int rem = idx - h * (NW_MASK * NN);
        int w   = rem / NN;
        int nm  = rem - w * NN;
        g_comb[idx] = bias_table[rel_index[nm] * H_HEADS + h] + mask[w * NN + nm];
    }
}

// ---------------------------------------------------------------------------
// Kernel 1/3: fp16 GEMM  C[m,n] = sum_k A[m,k]*B[n,k] + bias[n]
//   A (M,K), B (N,K) row-major fp16; C fp32. BM=BN=128, BK=64 halves
//   (128 B/row). 256 threads (8 warps 4x2, warp tile 32x64), 2-stage
//   cp.async, XOR-swizzled SMEM, ldmatrix.x4 fragment loads. 64 KB SMEM.
// ---------------------------------------------------------------------------
#define GBM 128
#define GBN 128
#define GBK 64
#define GSTG (GBM * GBK * 2)                  // 16384 bytes per tile
#define GEMM_SMEM_BYTES (4 * GSTG)            // 65536

__global__ __launch_bounds__(256, 2)
void gemm_f16_pipe(const __half* __restrict__ A, const __half* __restrict__ B,
                   const float* __restrict__ bias, float* __restrict__ C,
                   int M, int N, int K) {
    extern __shared__ float dynsmem[];
    const uint32_t as_base = (uint32_t)__cvta_generic_to_shared(dynsmem);
    const uint32_t bs_base = as_base + 2 * GSTG;

    const int tid  = threadIdx.x;
    const int lane = tid & 31;
    const int warp = tid >> 5;
    const int wm   = warp >> 1;
    const int wn   = warp & 1;
    const int bm   = blockIdx.y * GBM;
    const int bn   = blockIdx.x * GBN;
    const int r4   = lane >> 2;
    const int c4   = lane & 3;

    // loader: 128 rows x 8 granules(16B) per tile; 4 granules per thread
    const int lc4  = tid & 7;
    const int lrow = tid >> 3;
    const int pc4  = lc4 ^ (lrow & 7);

    // ldmatrix lane geometry (identical structure to tf32 version;
    // granule = 16 B = 8 halves)
    const int l7       = lane & 7;
    const int a_half_m = (lane >> 3) & 1;
    const int a_half_k = lane >> 4;
    const int b_half_k = (lane >> 3) & 1;
    const int b_sel    = lane >> 4;

    int rA7[2]; uint32_t baseA[2];
    #pragma unroll
    for (int mt = 0; mt < 2; mt++) {
        int row = wm * 32 + mt * 16 + a_half_m * 8 + l7;
        rA7[mt]   = row & 7;
        baseA[mt] = (uint32_t)row * 128;
    }
    int rB7[4]; uint32_t baseB[4];
    #pragma unroll
    for (int j = 0; j < 4; j++) {
        int row = wn * 64 + (2 * j + b_sel) * 8 + l7;
        rB7[j]   = row & 7;
        baseB[j] = (uint32_t)row * 128;
    }

    const int kTiles = K / GBK;

    auto issue = [&](int ktf, int s) {
        #pragma unroll
        for (int i = 0; i < 4; i++) {
            int r = lrow + i * 32;
            cp_async16(as_base + (uint32_t)(s * GSTG + r * 128 + pc4 * 16),
                       A + (size_t)(bm + r) * K + ktf + lc4 * 8);
        }
        #pragma unroll
        for (int i = 0; i < 4; i++) {
            int r = lrow + i * 32;
            cp_async16(bs_base + (uint32_t)(s * GSTG + r * 128 + pc4 * 16),
                       B + (size_t)(bn + r) * K + ktf + lc4 * 8);
        }
        asm volatile("cp.async.commit_group;\n" ::: "memory");
    };

    float acc[2][8][4];
    #pragma unroll
    for (int mt = 0; mt < 2; mt++)
        #pragma unroll
        for (int nt = 0; nt < 8; nt++)
            #pragma unroll
            for (int i = 0; i < 4; i++) acc[mt][nt][i] = 0.f;

    issue(0, 0);

    for (int t = 0; t < kTiles; t++) {
        const int s = t & 1;
        if (t + 1 < kTiles) {
            issue((t + 1) * GBK, s ^ 1);
            asm volatile("cp.async.wait_group 1;\n" ::: "memory");
        } else {
            asm volatile("cp.async.wait_group 0;\n" ::: "memory");
        }
        __syncthreads();

        const uint32_t asb = as_base + (uint32_t)(s * GSTG);
        const uint32_t bsb = bs_base + (uint32_t)(s * GSTG);
        #pragma unroll
        for (int step = 0; step < 4; step++) {   // 4 x K=16 per 64-half tile
            const int kk = step * 2;             // granule index 0,2,4,6
            uint32_t af[2][4];
            uint32_t bf[8][2];
            #pragma unroll
            for (int mt = 0; mt < 2; mt++) {
                uint32_t addr = asb + baseA[mt] +
                                (uint32_t)(((kk + a_half_k) ^ rA7[mt]) << 4);
                ldsm_x4(af[mt][0], af[mt][1], af[mt][2], af[mt][3], addr);
            }
            #pragma unroll
            for (int j = 0; j < 4; j++) {
                uint32_t addr = bsb + baseB[j] +
                                (uint32_t)(((kk + b_half_k) ^ rB7[j]) << 4);
                ldsm_x4(bf[2 * j][0], bf[2 * j][1], bf[2 * j + 1][0], bf[2 * j + 1][1], addr);
            }
            #pragma unroll
            for (int mt = 0; mt < 2; mt++)
                #pragma unroll
                for (int nt = 0; nt < 8; nt++)
                    mma_f16_16x8x16(acc[mt][nt], af[mt], bf[nt]);
        }
        __syncthreads();
    }

    // epilogue: add bias, store fp32
    #pragma unroll
    for (int mt = 0; mt < 2; mt++) {
        int row0 = bm + wm * 32 + mt * 16 + r4;
        #pragma unroll
        for (int nt = 0; nt < 8; nt++) {
            int col = bn + wn * 64 + nt * 8 + 2 * c4;
            float b0 = bias[col], b1 = bias[col + 1];
            float2 v01 = make_float2(acc[mt][nt][0] + b0, acc[mt][nt][1] + b1);
            float2 v23 = make_float2(acc[mt][nt][2] + b0, acc[mt][nt][3] + b1);
            *(float2*)(C + (size_t)row0 * N + col)       = v01;
            *(float2*)(C + (size_t)(row0 + 8) * N + col) = v23;
        }
    }
}

// ---------------------------------------------------------------------------
// Kernel 2: fused attention, 2 windows per CTA (b, b+2048 share comb tile)
//   grid (H=12, 64, 32), 256 threads; output stored fp16 to g_aoh.
// ---------------------------------------------------------------------------
#define QS_STR 36
#define SS_STR 57
#define ATTN_F_QS  (2 * N_TOK * QS_STR)
#define ATTN_F_VT  (2 * HD * SS_STR)
#define ATTN_F_SS  (2 * N_TOK * SS_STR)
#define ATTN_SMEM_FLOATS (2 * ATTN_F_QS + ATTN_F_VT + ATTN_F_SS + 2416)
#define ATTN_SMEM_BYTES  (4 * ATTN_SMEM_FLOATS)   // 74824

__global__ __launch_bounds__(256)
void attn_fused2_kernel() {
    extern __shared__ float sm[];
    float* cb = sm + 2 * ATTN_F_QS + ATTN_F_VT + ATTN_F_SS;

    const int h    = blockIdx.x;
    const int tid  = threadIdx.x;
    const int wg   = tid >> 7;
    const int tl   = tid & 127;
    const int lane = tid & 31;
    const int warp = (tid >> 5) & 3;
    const int r4   = lane >> 2;
    const int c4   = lane & 3;
    const float scale = 0.1767766952966369f;

    const int b = blockIdx.y + NW_MASK * (blockIdx.z + wg * 32);

    float* qsw = sm + wg * (N_TOK * QS_STR);
    float* ksw = sm + ATTN_F_QS + wg * (N_TOK * QS_STR);
    float* vtw = sm + 2 * ATTN_F_QS + wg * (HD * SS_STR);
    float* Ssw = sm + 2 * ATTN_F_QS + ATTN_F_VT + wg * (N_TOK * SS_STR);

    for (int i = tl; i < N_TOK * 8; i += 128) { int r = i >> 3; Ssw[r * SS_STR + 49 + (i & 7)] = 0.f; }
    for (int i = tl; i < HD * 8;    i += 128) { int r = i >> 3; vtw[r * SS_STR + 49 + (i & 7)] = 0.f; }

    const float* base = g_qkv + (size_t)b * N_TOK * (3 * DIM) + h * HD;
    #pragma unroll 4
    for (int idx = tl; idx < N_TOK * HD; idx += 128) {
        int n = idx >> 5;
        int d = idx & 31;
        const float* rp = base + (size_t)n * (3 * DIM) + d;
        qsw[n * QS_STR + d] = to_tf32(rp[0] * scale);
        ksw[n * QS_STR + d] = to_tf32(rp[DIM]);
        vtw[d * SS_STR + n] = to_tf32(rp[2 * DIM]);
    }
    const float* cbg = g_comb + (size_t)(h * NW_MASK + blockIdx.y) * NN;
    for (int i = tid; i < NN; i += 256) cb[i] = cbg[i];
    __syncthreads();

    {
        float acc[7][4];
        #pragma unroll
        for (int nt = 0; nt < 7; nt++)
            #pragma unroll
            for (int i = 0; i < 4; i++) acc[nt][i] = 0.f;

        const int am  = warp * 16;
        const int ar0 = min(am + r4, N_TOK - 1);
        const int ar1 = min(am + r4 + 8, N_TOK - 1);
        #pragma unroll
        for (int k8 = 0; k8 < 32; k8 += 8) {
            uint32_t af[4], bf[7][2];
            af[0] = __float_as_uint(qsw[ar0 * QS_STR + k8 + c4    ]);
            af[1] = __float_as_uint(qsw[ar1 * QS_STR + k8 + c4    ]);
            af[2] = __float_as_uint(qsw[ar0 * QS_STR + k8 + c4 + 4]);
            af[3] = __float_as_uint(qsw[ar1 * QS_STR + k8 + c4 + 4]);
            #pragma unroll
            for (int nt = 0; nt < 7; nt++) {
                int br = min(nt * 8 + r4, N_TOK - 1);
                bf[nt][0] = __float_as_uint(ksw[br * QS_STR + k8 + c4    ]);
                bf[nt][1] = __float_as_uint(ksw[br * QS_STR + k8 + c4 + 4]);
            }
            #pragma unroll
            for (int nt = 0; nt < 7; nt++)
                mma_tf32_16x8x8(acc[nt], af, bf[nt]);
        }

        const int n0  = am + r4;
        const int n1  = n0 + 8;
        const int cr0 = min(n0, N_TOK - 1) * N_TOK;
        const int cr1 = min(n1, N_TOK - 1) * N_TOK;
        float s0 = 0.f, s1 = 0.f;
        #pragma unroll
        for (int nt = 0; nt < 7; nt++) {
            int col0 = nt * 8 + 2 * c4;
            int col1 = col0 + 1;
            float e00 = (col0 < N_TOK) ? __expf(acc[nt][0] + cb[cr0 + col0]) : 0.f;
            float e01 = (col1 < N_TOK) ? __expf(acc[nt][1] + cb[cr0 + col1]) : 0.f;
            float e10 = (col0 < N_TOK) ? __expf(acc[nt][2] + cb[cr1 + col0]) : 0.f;
            float e11 = (col1 < N_TOK) ? __expf(acc[nt][3] + cb[cr1 + col1]) : 0.f;
            acc[nt][0] = e00; acc[nt][1] = e01; acc[nt][2] = e10; acc[nt][3] = e11;
            s0 += e00 + e01;
            s1 += e10 + e11;
        }
        s0 += __shfl_xor_sync(0xffffffffu, s0, 1);
        s0 += __shfl_xor_sync(0xffffffffu, s0, 2);
        s1 += __shfl_xor_sync(0xffffffffu, s1, 1);
        s1 += __shfl_xor_sync(0xffffffffu, s1, 2);
        float inv0 = __frcp_rn(s0);
        float inv1 = __frcp_rn(s1);

        #pragma unroll
        for (int nt = 0; nt < 7; nt++) {
            int col0 = nt * 8 + 2 * c4;
            int col1 = col0 + 1;
            if (n0 < N_TOK && col0 < N_TOK) Ssw[n0 * SS_STR + col0] = to_tf32(acc[nt][0] * inv0);
            if (n0 < N_TOK && col1 < N_TOK) Ssw[n0 * SS_STR + col1] = to_tf32(acc[nt][1] * inv0);
            if (n1 < N_TOK && col0 < N_TOK) Ssw[n1 * SS_STR + col0] = to_tf32(acc[nt][2] * inv1);
            if (n1 < N_TOK && col1 < N_TOK) Ssw[n1 * SS_STR + col1] = to_tf32(acc[nt][3] * inv1);
        }
    }
    __syncthreads();

    {
        float acc[4][4];
        #pragma unroll
        for (int nt = 0; nt < 4; nt++)
            #pragma unroll
            for (int i = 0; i < 4; i++) acc[nt][i] = 0.f;

        const int am  = warp * 16;
        const int ar0 = min(am + r4, N_TOK - 1);
        const int ar1 = min(am + r4 + 8, N_TOK - 1);
        #pragma unroll
        for (int k8 = 0; k8 < 56; k8 += 8) {
            uint32_t af[4], bf[4][2];
            af[0] = __float_as_uint(Ssw[ar0 * SS_STR + k8 + c4    ]);
            af[1] = __float_as_uint(Ssw[ar1 * SS_STR + k8 + c4    ]);
            af[2] = __float_as_uint(Ssw[ar0 * SS_STR + k8 + c4 + 4]);
            af[3] = __float_as_uint(Ssw[ar1 * SS_STR + k8 + c4 + 4]);
            #pragma unroll
            for (int nt = 0; nt < 4; nt++) {
                bf[nt][0] = __float_as_uint(vtw[(nt * 8 + r4) * SS_STR + k8 + c4    ]);
                bf[nt][1] = __float_as_uint(vtw[(nt * 8 + r4) * SS_STR + k8 + c4 + 4]);
            }
            #pragma unroll
            for (int nt = 0; nt < 4; nt++)
                mma_tf32_16x8x8(acc[nt], af, bf[nt]);
        }
        __half* aob = g_aoh + (size_t)b * N_TOK * DIM + h * HD;
        const int n0 = am + r4, n1 = n0 + 8;
        #pragma unroll
        for (int nt = 0; nt < 4; nt++) {
            int col = nt * 8 + 2 * c4;
            if (n0 < N_TOK)
                *(__half2*)(aob + (size_t)n0 * DIM + col) =
                    __floats2half2_rn(acc[nt][0], acc[nt][1]);
            if (n1 < N_TOK)
                *(__half2*)(aob + (size_t)n1 * DIM + col) =
                    __floats2half2_rn(acc[nt][2], acc[nt][3]);
        }
    }
}

// ---------------------------------------------------------------------------
// launch
// ---------------------------------------------------------------------------
extern "C" void kernel_launch(void* const* d_in, const int* in_sizes, int n_in,
                              void* d_out, int out_size) {
    const float* x          = (const float*)d_in[0];
    const float* mask       = (const float*)d_in[1];
    const float* qkv_w      = (const float*)d_in[2];
    const float* qkv_b      = (const float*)d_in[3];
    const float* proj_w     = (const float*)d_in[4];
    const float* proj_b     = (const float*)d_in[5];
    const float* bias_table = (const float*)d_in[6];
    const int*   rel_index  = (const int*)d_in[7];
    float* out = (float*)d_out;

    void* p_qkv = nullptr; void* p_aoh = nullptr;
    void* p_xh  = nullptr; void* p_wh  = nullptr;
    cudaGetSymbolAddress(&p_qkv, g_qkv);
    cudaGetSymbolAddress(&p_aoh, g_aoh);
    cudaGetSymbolAddress(&p_xh,  g_xh);
    cudaGetSymbolAddress(&p_wh,  g_wh);
    float*  qkv  = (float*)p_qkv;
    __half* aoh  = (__half*)p_aoh;
    __half* xh   = (__half*)p_xh;
    __half* qkvw_h = (__half*)p_wh;
    __half* projw_h = qkvw_h + 3 * DIM * DIM;

    cudaFuncSetAttribute(gemm_f16_pipe,
                         cudaFuncAttributeMaxDynamicSharedMemorySize,
                         GEMM_SMEM_BYTES);
    cudaFuncSetAttribute(attn_fused2_kernel,
                         cudaFuncAttributeMaxDynamicSharedMemorySize,
                         ATTN_SMEM_BYTES);

    f32_to_f16_kernel<<<2048, 256>>>(x, xh, (T_TOT * DIM) / 4);
    f32_to_f16_kernel<<<256, 256>>>(qkv_w, qkvw_h, (3 * DIM * DIM) / 4);
    f32_to_f16_kernel<<<256, 256>>>(proj_w, projw_h, (DIM * DIM) / 4);
    {
        int n = H_HEADS * NW_MASK * NN;
        comb_kernel<<<(n + 255) / 256, 256>>>(bias_table, rel_index, mask);
    }
    // 1) QKV GEMM: (T,384) @ (1152,384)^T -> (T,1152)
    {
        dim3 grid((3 * DIM) / GBN, T_TOT / GBM);
        gemm_f16_pipe<<<grid, 256, GEMM_SMEM_BYTES>>>(xh, qkvw_h, qkv_b, qkv,
                                                      T_TOT, 3 * DIM, DIM);
    }
    // 2) fused attention: 2 windows per CTA
    {
        dim3 grid(H_HEADS, NW_MASK, B_WIN / NW_MASK / 2);
        attn_fused2_kernel<<<grid, 256, ATTN_SMEM_BYTES>>>();
    }
    // 3) proj GEMM: (T,384) @ (384,384)^T -> (T,384)
    {
        dim3 grid(DIM / GBN, T_TOT / GBM);
        gemm_f16_pipe<<<grid, 256, GEMM_SMEM_BYTES>>>(aoh, projw_h, proj_b, out,
                                                      T_TOT, DIM, DIM);
    }
}

// round 14
// speedup vs baseline: 1.7244x; 1.1806x over previous
#include <cuda_runtime.h>
#include <cuda_bf16.h>
#include <cuda_fp16.h>
#include <cstdint>
#include <cstddef>

// ---------------------------------------------------------------------------
// WindowAttention (Swin-style): B_=4096 windows, N=49, C=384, H=12, hd=32
// Round 14: full fp16 datapath. QKV GEMM outputs fp16; attention uses
//           fp16 m16n8k16 mma for QK^T and PV (fp32 accum, fp32 softmax).
// ---------------------------------------------------------------------------

#define B_WIN   4096
#define N_TOK   49
#define DIM     384
#define H_HEADS 12
#define HD      32
#define T_TOT   (B_WIN * N_TOK)      // 200704 tokens
#define NW_MASK 64
#define NN      (N_TOK * N_TOK)      // 2401

__device__ __half g_qkvh[(size_t)T_TOT * 3 * DIM];  // (T, 1152) fp16
__device__ __half g_aoh [(size_t)T_TOT * DIM];      // (T, 384) fp16
__device__ __half g_xh  [(size_t)T_TOT * DIM];      // x, fp16
__device__ __half g_wh  [3 * DIM * DIM + DIM * DIM];// qkv_w | proj_w fp16
__device__ float  g_comb[(size_t)H_HEADS * NW_MASK * NN];  // bias+mask

// ---------------------------------------------------------------------------
// helpers
// ---------------------------------------------------------------------------
__device__ __forceinline__ void mma_f16_16x8x16(float d[4], const uint32_t a[4],
                                                const uint32_t b[2]) {
    asm volatile(
        "mma.sync.aligned.m16n8k16.row.col.f32.f16.f16.f32 "
        "{%0,%1,%2,%3}, {%4,%5,%6,%7}, {%8,%9}, {%0,%1,%2,%3};\n"
        : "+f"(d[0]), "+f"(d[1]), "+f"(d[2]), "+f"(d[3])
        : "r"(a[0]), "r"(a[1]), "r"(a[2]), "r"(a[3]), "r"(b[0]), "r"(b[1]));
}

__device__ __forceinline__ void ldsm_x4(uint32_t& r0, uint32_t& r1,
                                        uint32_t& r2, uint32_t& r3, uint32_t addr) {
    asm volatile("ldmatrix.sync.aligned.m8n8.x4.shared.b16 {%0,%1,%2,%3}, [%4];\n"
                 : "=r"(r0), "=r"(r1), "=r"(r2), "=r"(r3) : "r"(addr));
}

__device__ __forceinline__ void cp_async16(uint32_t smem_addr, const void* gptr) {
    asm volatile("cp.async.cg.shared.global [%0], [%1], 16;\n"
                 :: "r"(smem_addr), "l"(gptr) : "memory");
}

// ---------------------------------------------------------------------------
// Kernel R: convert fp32 -> fp16 (RN), 4 floats per thread-step
// ---------------------------------------------------------------------------
__global__ void f32_to_f16_kernel(const float* __restrict__ src,
                                  __half* __restrict__ dst, int n4) {
    int i = blockIdx.x * blockDim.x + threadIdx.x;
    int stride = gridDim.x * blockDim.x;
    for (; i < n4; i += stride) {
        float4 v = ((const float4*)src)[i];
        __half2 h01 = __floats2half2_rn(v.x, v.y);
        __half2 h23 = __floats2half2_rn(v.z, v.w);
        uint2 o;
        o.x = *(uint32_t*)&h01;
        o.y = *(uint32_t*)&h23;
        ((uint2*)dst)[i] = o;
    }
}

// ---------------------------------------------------------------------------
// Kernel 0: comb[h][w][n][m] = bias_table[rel_index[n,m]][h] + mask[w][n][m]
// ---------------------------------------------------------------------------
__global__ void comb_kernel(const float* __restrict__ bias_table,
                            const int* __restrict__ rel_index,
                            const float* __restrict__ mask) {
    int idx = blockIdx.x * blockDim.x + threadIdx.x;
    if (idx < H_HEADS * NW_MASK * NN) {
        int h   = idx / (NW_MASK * NN);
        int rem = idx - h * (NW_MASK * NN);
        int w   = rem / NN;
        int nm  = rem - w * NN;
        g_comb[idx] = bias_table[rel_index[nm] * H_HEADS + h] + mask[w * NN + nm];
    }
}

// ---------------------------------------------------------------------------
// Kernel 1/3: fp16 GEMM  C[m,n] = sum_k A[m,k]*B[n,k] + bias[n]
//   OUT_HALF selects fp16 or fp32 output. BM=BN=128, BK=64 halves.
// ---------------------------------------------------------------------------
#define GBM 128
#define GBN 128
#define GBK 64
#define GSTG (GBM * GBK * 2)                  // 16384 bytes per tile
#define GEMM_SMEM_BYTES (4 * GSTG)            // 65536

template <bool OUT_HALF>
__global__ __launch_bounds__(256, 2)
void gemm_f16_pipe(const __half* __restrict__ A, const __half* __restrict__ B,
                   const float* __restrict__ bias, void* __restrict__ Cv,
                   int M, int N, int K) {
    extern __shared__ float dynsmem[];
    const uint32_t as_base = (uint32_t)__cvta_generic_to_shared(dynsmem);
    const uint32_t bs_base = as_base + 2 * GSTG;

    const int tid  = threadIdx.x;
    const int lane = tid & 31;
    const int warp = tid >> 5;
    const int wm   = warp >> 1;
    const int wn   = warp & 1;
    const int bm   = blockIdx.y * GBM;
    const int bn   = blockIdx.x * GBN;
    const int r4   = lane >> 2;
    const int c4   = lane & 3;

    const int lc4  = tid & 7;
    const int lrow = tid >> 3;
    const int pc4  = lc4 ^ (lrow & 7);

    const int l7       = lane & 7;
    const int a_half_m = (lane >> 3) & 1;
    const int a_half_k = lane >> 4;
    const int b_half_k = (lane >> 3) & 1;
    const int b_sel    = lane >> 4;

    int rA7[2]; uint32_t baseA[2];
    #pragma unroll
    for (int mt = 0; mt < 2; mt++) {
        int row = wm * 32 + mt * 16 + a_half_m * 8 + l7;
        rA7[mt]   = row & 7;
        baseA[mt] = (uint32_t)row * 128;
    }
    int rB7[4]; uint32_t baseB[4];
    #pragma unroll
    for (int j = 0; j < 4; j++) {
        int row = wn * 64 + (2 * j + b_sel) * 8 + l7;
        rB7[j]   = row & 7;
        baseB[j] = (uint32_t)row * 128;
    }

    const int kTiles = K / GBK;

    auto issue = [&](int ktf, int s) {
        #pragma unroll
        for (int i = 0; i < 4; i++) {
            int r = lrow + i * 32;
            cp_async16(as_base + (uint32_t)(s * GSTG + r * 128 + pc4 * 16),
                       A + (size_t)(bm + r) * K + ktf + lc4 * 8);
        }
        #pragma unroll
        for (int i = 0; i < 4; i++) {
            int r = lrow + i * 32;
            cp_async16(bs_base + (uint32_t)(s * GSTG + r * 128 + pc4 * 16),
                       B + (size_t)(bn + r) * K + ktf + lc4 * 8);
        }
        asm volatile("cp.async.commit_group;\n" ::: "memory");
    };

    float acc[2][8][4];
    #pragma unroll
    for (int mt = 0; mt < 2; mt++)
        #pragma unroll
        for (int nt = 0; nt < 8; nt++)
            #pragma unroll
            for (int i = 0; i < 4; i++) acc[mt][nt][i] = 0.f;

    issue(0, 0);

    for (int t = 0; t < kTiles; t++) {
        const int s = t & 1;
        if (t + 1 < kTiles) {
            issue((t + 1) * GBK, s ^ 1);
            asm volatile("cp.async.wait_group 1;\n" ::: "memory");
        } else {
            asm volatile("cp.async.wait_group 0;\n" ::: "memory");
        }
        __syncthreads();

        const uint32_t asb = as_base + (uint32_t)(s * GSTG);
        const uint32_t bsb = bs_base + (uint32_t)(s * GSTG);
        #pragma unroll
        for (int step = 0; step < 4; step++) {
            const int kk = step * 2;
            uint32_t af[2][4];
            uint32_t bf[8][2];
            #pragma unroll
            for (int mt = 0; mt < 2; mt++) {
                uint32_t addr = asb + baseA[mt] +
                                (uint32_t)(((kk + a_half_k) ^ rA7[mt]) << 4);
                ldsm_x4(af[mt][0], af[mt][1], af[mt][2], af[mt][3], addr);
            }
            #pragma unroll
            for (int j = 0; j < 4; j++) {
                uint32_t addr = bsb + baseB[j] +
                                (uint32_t)(((kk + b_half_k) ^ rB7[j]) << 4);
                ldsm_x4(bf[2 * j][0], bf[2 * j][1], bf[2 * j + 1][0], bf[2 * j + 1][1], addr);
            }
            #pragma unroll
            for (int mt = 0; mt < 2; mt++)
                #pragma unroll
                for (int nt = 0; nt < 8; nt++)
                    mma_f16_16x8x16(acc[mt][nt], af[mt], bf[nt]);
        }
        __syncthreads();
    }

    // epilogue: add bias, store fp16 or fp32
    #pragma unroll
    for (int mt = 0; mt < 2; mt++) {
        int row0 = bm + wm * 32 + mt * 16 + r4;
        #pragma unroll
        for (int nt = 0; nt < 8; nt++) {
            int col = bn + wn * 64 + nt * 8 + 2 * c4;
            float b0 = bias[col], b1 = bias[col + 1];
            float v0 = acc[mt][nt][0] + b0, v1 = acc[mt][nt][1] + b1;
            float v2 = acc[mt][nt][2] + b0, v3 = acc[mt][nt][3] + b1;
            if (OUT_HALF) {
                __half* C = (__half*)Cv;
                *(__half2*)(C + (size_t)row0 * N + col)       = __floats2half2_rn(v0, v1);
                *(__half2*)(C + (size_t)(row0 + 8) * N + col) = __floats2half2_rn(v2, v3);
            } else {
                float* C = (float*)Cv;
                *(float2*)(C + (size_t)row0 * N + col)       = make_float2(v0, v1);
                *(float2*)(C + (size_t)(row0 + 8) * N + col) = make_float2(v2, v3);
            }
        }
    }
}

// ---------------------------------------------------------------------------
// Kernel 2: fused attention (fp16 mma), 2 windows per CTA
//   grid (H=12, 64, 32), 256 threads; per-window halves in SMEM.
// ---------------------------------------------------------------------------
#define QS2_STR 40   // halves: (20r+c)%32 conflict-free fragment loads
#define SS2_STR 72   // halves: K padded to 64; (4r+c)%32 conflict-free
// halves per region (both windows)
#define A2_QS (2 * N_TOK * QS2_STR)   // 3920
#define A2_VT (2 * HD * SS2_STR)      // 4608
#define A2_SS (2 * N_TOK * SS2_STR)   // 7056
#define ATTN_SMEM_BYTES (2 * (2 * A2_QS + A2_VT + A2_SS) + 2416 * 4)  // 48672

__global__ __launch_bounds__(256)
void attn_fused2_kernel() {
    extern __shared__ __align__(16) char smraw[];
    __half* hs = (__half*)smraw;
    float*  cb = (float*)(smraw + 2 * (2 * A2_QS + A2_VT + A2_SS));

    const int h    = blockIdx.x;
    const int tid  = threadIdx.x;
    const int wg   = tid >> 7;
    const int tl   = tid & 127;
    const int lane = tid & 31;
    const int warp = (tid >> 5) & 3;
    const int r4   = lane >> 2;
    const int c4   = lane & 3;
    const float scale = 0.1767766952966369f;

    const int b = blockIdx.y + NW_MASK * (blockIdx.z + wg * 32);

    __half* qsw = hs + wg * (N_TOK * QS2_STR);
    __half* ksw = hs + A2_QS + wg * (N_TOK * QS2_STR);
    __half* vtw = hs + 2 * A2_QS + wg * (HD * SS2_STR);
    __half* Ssw = hs + 2 * A2_QS + A2_VT + wg * (N_TOK * SS2_STR);

    // zero pad cols 48..63 of Ss (rows 0..48) and vt (rows 0..31)
    for (int i = tl; i < N_TOK * 8; i += 128) {
        int r = i >> 3;
        *(uint32_t*)&Ssw[r * SS2_STR + 48 + 2 * (i & 7)] = 0u;
    }
    for (int i = tl; i < HD * 8; i += 128) {
        int r = i >> 3;
        *(uint32_t*)&vtw[r * SS2_STR + 48 + 2 * (i & 7)] = 0u;
    }

    // load q,k,v (fp16, half2 granularity); q scaled in fp32 then re-rounded
    const __half* base = g_qkvh + (size_t)b * N_TOK * (3 * DIM) + h * HD;
    #pragma unroll 4
    for (int idx = tl; idx < N_TOK * (HD / 2); idx += 128) {
        int n  = idx >> 4;
        int d2 = idx & 15;
        const __half* rp = base + (size_t)n * (3 * DIM) + 2 * d2;
        __half2 hq = *(const __half2*)(rp);
        __half2 hk = *(const __half2*)(rp + DIM);
        __half2 hv = *(const __half2*)(rp + 2 * DIM);
        float2 fq = __half22float2(hq);
        *(__half2*)&qsw[n * QS2_STR + 2 * d2] = __floats2half2_rn(fq.x * scale, fq.y * scale);
        *(__half2*)&ksw[n * QS2_STR + 2 * d2] = hk;
        vtw[(2 * d2    ) * SS2_STR + n] = __low2half(hv);
        vtw[(2 * d2 + 1) * SS2_STR + n] = __high2half(hv);
    }
    const float* cbg = g_comb + (size_t)(h * NW_MASK + blockIdx.y) * NN;
    for (int i = tid; i < NN; i += 256) cb[i] = cbg[i];
    __syncthreads();

    // --- S = (q*scale) @ k^T (fp16 mma, K=32 = 2 k16 steps); fused softmax ---
    {
        float acc[7][4];
        #pragma unroll
        for (int nt = 0; nt < 7; nt++)
            #pragma unroll
            for (int i = 0; i < 4; i++) acc[nt][i] = 0.f;

        const int am  = warp * 16;
        const int ar0 = min(am + r4, N_TOK - 1);
        const int ar1 = min(am + r4 + 8, N_TOK - 1);
        #pragma unroll
        for (int s = 0; s < 2; s++) {
            const int k0 = 2 * c4 + 16 * s;
            uint32_t af[4], bf[7][2];
            af[0] = *(const uint32_t*)&qsw[ar0 * QS2_STR + k0    ];
            af[1] = *(const uint32_t*)&qsw[ar1 * QS2_STR + k0    ];
            af[2] = *(const uint32_t*)&qsw[ar0 * QS2_STR + k0 + 8];
            af[3] = *(const uint32_t*)&qsw[ar1 * QS2_STR + k0 + 8];
            #pragma unroll
            for (int nt = 0; nt < 7; nt++) {
                int br = min(nt * 8 + r4, N_TOK - 1);
                bf[nt][0] = *(const uint32_t*)&ksw[br * QS2_STR + k0    ];
                bf[nt][1] = *(const uint32_t*)&ksw[br * QS2_STR + k0 + 8];
            }
            #pragma unroll
            for (int nt = 0; nt < 7; nt++)
                mma_f16_16x8x16(acc[nt], af, bf[nt]);
        }

        // fused softmax (fp32): exp(S + comb), quad-shuffle row sums
        const int n0  = am + r4;
        const int n1  = n0 + 8;
        const int cr0 = min(n0, N_TOK - 1) * N_TOK;
        const int cr1 = min(n1, N_TOK - 1) * N_TOK;
        float s0 = 0.f, s1 = 0.f;
        #pragma unroll
        for (int nt = 0; nt < 7; nt++) {
            int col0 = nt * 8 + 2 * c4;
            int col1 = col0 + 1;
            float e00 = (col0 < N_TOK) ? __expf(acc[nt][0] + cb[cr0 + col0]) : 0.f;
            float e01 = (col1 < N_TOK) ? __expf(acc[nt][1] + cb[cr0 + col1]) : 0.f;
            float e10 = (col0 < N_TOK) ? __expf(acc[nt][2] + cb[cr1 + col0]) : 0.f;
            float e11 = (col1 < N_TOK) ? __expf(acc[nt][3] + cb[cr1 + col1]) : 0.f;
            acc[nt][0] = e00; acc[nt][1] = e01; acc[nt][2] = e10; acc[nt][3] = e11;
            s0 += e00 + e01;
            s1 += e10 + e11;
        }
        s0 += __shfl_xor_sync(0xffffffffu, s0, 1);
        s0 += __shfl_xor_sync(0xffffffffu, s0, 2);
        s1 += __shfl_xor_sync(0xffffffffu, s1, 1);
        s1 += __shfl_xor_sync(0xffffffffu, s1, 2);
        float inv0 = __frcp_rn(s0);
        float inv1 = __frcp_rn(s1);

        // store P as fp16 half2 (pad col written as 0 where col1 invalid)
        #pragma unroll
        for (int nt = 0; nt < 7; nt++) {
            int col0 = nt * 8 + 2 * c4;
            int col1 = col0 + 1;
            if (col0 < N_TOK) {
                float p01 = (col1 < N_TOK) ? acc[nt][1] * inv0 : 0.f;
                float p11 = (col1 < N_TOK) ? acc[nt][3] * inv1 : 0.f;
                if (n0 < N_TOK)
                    *(__half2*)&Ssw[n0 * SS2_STR + col0] =
                        __floats2half2_rn(acc[nt][0] * inv0, p01);
                if (n1 < N_TOK)
                    *(__half2*)&Ssw[n1 * SS2_STR + col0] =
                        __floats2half2_rn(acc[nt][2] * inv1, p11);
            }
        }
    }
    __syncthreads();

    // --- O = P @ V (fp16 mma, K=64 = 4 k16 steps); store fp16 ---
    {
        float acc[4][4];
        #pragma unroll
        for (int nt = 0; nt < 4; nt++)
            #pragma unroll
            for (int i = 0; i < 4; i++) acc[nt][i] = 0.f;

        const int am  = warp * 16;
        const int ar0 = min(am + r4, N_TOK - 1);
        const int ar1 = min(am + r4 + 8, N_TOK - 1);
        #pragma unroll
        for (int s = 0; s < 4; s++) {
            const int k0 = 2 * c4 + 16 * s;
            uint32_t af[4], bf[4][2];
            af[0] = *(const uint32_t*)&Ssw[ar0 * SS2_STR + k0    ];
            af[1] = *(const uint32_t*)&Ssw[ar1 * SS2_STR + k0    ];
            af[2] = *(const uint32_t*)&Ssw[ar0 * SS2_STR + k0 + 8];
            af[3] = *(const uint32_t*)&Ssw[ar1 * SS2_STR + k0 + 8];
            #pragma unroll
            for (int nt = 0; nt < 4; nt++) {
                bf[nt][0] = *(const uint32_t*)&vtw[(nt * 8 + r4) * SS2_STR + k0    ];
                bf[nt][1] = *(const uint32_t*)&vtw[(nt * 8 + r4) * SS2_STR + k0 + 8];
            }
            #pragma unroll
            for (int nt = 0; nt < 4; nt++)
                mma_f16_16x8x16(acc[nt], af, bf[nt]);
        }
        __half* aob = g_aoh + (size_t)b * N_TOK * DIM + h * HD;
        const int n0 = am + r4, n1 = n0 + 8;
        #pragma unroll
        for (int nt = 0; nt < 4; nt++) {
            int col = nt * 8 + 2 * c4;
            if (n0 < N_TOK)
                *(__half2*)(aob + (size_t)n0 * DIM + col) =
                    __floats2half2_rn(acc[nt][0], acc[nt][1]);
            if (n1 < N_TOK)
                *(__half2*)(aob + (size_t)n1 * DIM + col) =
                    __floats2half2_rn(acc[nt][2], acc[nt][3]);
        }
    }
}

// ---------------------------------------------------------------------------
// launch
// ---------------------------------------------------------------------------
extern "C" void kernel_launch(void* const* d_in, const int* in_sizes, int n_in,
                              void* d_out, int out_size) {
    const float* x          = (const float*)d_in[0];
    const float* mask       = (const float*)d_in[1];
    const float* qkv_w      = (const float*)d_in[2];
    const float* qkv_b      = (const float*)d_in[3];
    const float* proj_w     = (const float*)d_in[4];
    const float* proj_b     = (const float*)d_in[5];
    const float* bias_table = (const float*)d_in[6];
    const int*   rel_index  = (const int*)d_in[7];
    float* out = (float*)d_out;

    void* p_qkvh = nullptr; void* p_aoh = nullptr;
    void* p_xh   = nullptr; void* p_wh  = nullptr;
    cudaGetSymbolAddress(&p_qkvh, g_qkvh);
    cudaGetSymbolAddress(&p_aoh,  g_aoh);
    cudaGetSymbolAddress(&p_xh,   g_xh);
    cudaGetSymbolAddress(&p_wh,   g_wh);
    __half* qkvh = (__half*)p_qkvh;
    __half* aoh  = (__half*)p_aoh;
    __half* xh   = (__half*)p_xh;
    __half* qkvw_h  = (__half*)p_wh;
    __half* projw_h = qkvw_h + 3 * DIM * DIM;

    cudaFuncSetAttribute(gemm_f16_pipe<true>,
                         cudaFuncAttributeMaxDynamicSharedMemorySize,
                         GEMM_SMEM_BYTES);
    cudaFuncSetAttribute(gemm_f16_pipe<false>,
                         cudaFuncAttributeMaxDynamicSharedMemorySize,
                         GEMM_SMEM_BYTES);
    cudaFuncSetAttribute(attn_fused2_kernel,
                         cudaFuncAttributeMaxDynamicSharedMemorySize,
                         ATTN_SMEM_BYTES);

    f32_to_f16_kernel<<<2048, 256>>>(x, xh, (T_TOT * DIM) / 4);
    f32_to_f16_kernel<<<256, 256>>>(qkv_w, qkvw_h, (3 * DIM * DIM) / 4);
    f32_to_f16_kernel<<<256, 256>>>(proj_w, projw_h, (DIM * DIM) / 4);
    {
        int n = H_HEADS * NW_MASK * NN;
        comb_kernel<<<(n + 255) / 256, 256>>>(bias_table, rel_index, mask);
    }
    // 1) QKV GEMM: (T,384) @ (1152,384)^T -> (T,1152) fp16
    {
        dim3 grid((3 * DIM) / GBN, T_TOT / GBM);
        gemm_f16_pipe<true><<<grid, 256, GEMM_SMEM_BYTES>>>(
            xh, qkvw_h, qkv_b, qkvh, T_TOT, 3 * DIM, DIM);
    }
    // 2) fused attention: 2 windows per CTA, fp16 mma
    {
        dim3 grid(H_HEADS, NW_MASK, B_WIN / NW_MASK / 2);
        attn_fused2_kernel<<<grid, 256, ATTN_SMEM_BYTES>>>();
    }
    // 3) proj GEMM: (T,384) @ (384,384)^T -> (T,384) fp32
    {
        dim3 grid(DIM / GBN, T_TOT / GBM);
        gemm_f16_pipe<false><<<grid, 256, GEMM_SMEM_BYTES>>>(
            aoh, projw_h, proj_b, out, T_TOT, DIM, DIM);
    }
}

// round 15
// speedup vs baseline: 1.7479x; 1.0136x over previous
#include <cuda_runtime.h>
#include <cuda_bf16.h>
#include <cuda_fp16.h>
#include <cstdint>
#include <cstddef>

// ---------------------------------------------------------------------------
// WindowAttention (Swin-style): B_=4096 windows, N=49, C=384, H=12, hd=32
// Round 15: permuted fp16 qkv layout [3][H][B_][49][32] (contiguous per
//           window-head), q pre-scaled in GEMM epilogue; attention uses
//           ldmatrix (x4 / x4.trans) for all fragments — no v transpose.
// ---------------------------------------------------------------------------

#define B_WIN   4096
#define N_TOK   49
#define DIM     384
#define H_HEADS 12
#define HD      32
#define T_TOT   (B_WIN * N_TOK)      // 200704 tokens
#define NW_MASK 64
#define NN      (N_TOK * N_TOK)      // 2401
#define WHD     (N_TOK * HD)         // 1568 halves per (mtx,h,b)

__device__ __half g_qkvh[(size_t)3 * H_HEADS * B_WIN * WHD]; // permuted qkv
__device__ __half g_aoh [(size_t)T_TOT * DIM];      // (T, 384) fp16
__device__ __half g_xh  [(size_t)T_TOT * DIM];      // x, fp16
__device__ __half g_wh  [3 * DIM * DIM + DIM * DIM];// qkv_w | proj_w fp16
__device__ float  g_comb[(size_t)H_HEADS * NW_MASK * NN];  // bias+mask

// ---------------------------------------------------------------------------
// helpers
// ---------------------------------------------------------------------------
__device__ __forceinline__ void mma_f16_16x8x16(float d[4], const uint32_t a[4],
                                                const uint32_t b[2]) {
    asm volatile(
        "mma.sync.aligned.m16n8k16.row.col.f32.f16.f16.f32 "
        "{%0,%1,%2,%3}, {%4,%5,%6,%7}, {%8,%9}, {%0,%1,%2,%3};\n"
        : "+f"(d[0]), "+f"(d[1]), "+f"(d[2]), "+f"(d[3])
        : "r"(a[0]), "r"(a[1]), "r"(a[2]), "r"(a[3]), "r"(b[0]), "r"(b[1]));
}

__device__ __forceinline__ void ldsm_x4(uint32_t& r0, uint32_t& r1,
                                        uint32_t& r2, uint32_t& r3, uint32_t addr) {
    asm volatile("ldmatrix.sync.aligned.m8n8.x4.shared.b16 {%0,%1,%2,%3}, [%4];\n"
                 : "=r"(r0), "=r"(r1), "=r"(r2), "=r"(r3) : "r"(addr));
}

__device__ __forceinline__ void ldsm_x4t(uint32_t& r0, uint32_t& r1,
                                         uint32_t& r2, uint32_t& r3, uint32_t addr) {
    asm volatile("ldmatrix.sync.aligned.m8n8.x4.trans.shared.b16 {%0,%1,%2,%3}, [%4];\n"
                 : "=r"(r0), "=r"(r1), "=r"(r2), "=r"(r3) : "r"(addr));
}

__device__ __forceinline__ void ldsm_x2(uint32_t& r0, uint32_t& r1, uint32_t addr) {
    asm volatile("ldmatrix.sync.aligned.m8n8.x2.shared.b16 {%0,%1}, [%2];\n"
                 : "=r"(r0), "=r"(r1) : "r"(addr));
}

__device__ __forceinline__ void cp_async16(uint32_t smem_addr, const void* gptr) {
    asm volatile("cp.async.cg.shared.global [%0], [%1], 16;\n"
                 :: "r"(smem_addr), "l"(gptr) : "memory");
}

// ---------------------------------------------------------------------------
// Kernel R: convert fp32 -> fp16 (RN)
// ---------------------------------------------------------------------------
__global__ void f32_to_f16_kernel(const float* __restrict__ src,
                                  __half* __restrict__ dst, int n4) {
    int i = blockIdx.x * blockDim.x + threadIdx.x;
    int stride = gridDim.x * blockDim.x;
    for (; i < n4; i += stride) {
        float4 v = ((const float4*)src)[i];
        __half2 h01 = __floats2half2_rn(v.x, v.y);
        __half2 h23 = __floats2half2_rn(v.z, v.w);
        uint2 o;
        o.x = *(uint32_t*)&h01;
        o.y = *(uint32_t*)&h23;
        ((uint2*)dst)[i] = o;
    }
}

// ---------------------------------------------------------------------------
// Kernel 0: comb[h][w][n][m] = bias_table[rel_index[n,m]][h] + mask[w][n][m]
// ---------------------------------------------------------------------------
__global__ void comb_kernel(const float* __restrict__ bias_table,
                            const int* __restrict__ rel_index,
                            const float* __restrict__ mask) {
    int idx = blockIdx.x * blockDim.x + threadIdx.x;
    if (idx < H_HEADS * NW_MASK * NN) {
        int h   = idx / (NW_MASK * NN);
        int rem = idx - h * (NW_MASK * NN);
        int w   = rem / NN;
        int nm  = rem - w * NN;
        g_comb[idx] = bias_table[rel_index[nm] * H_HEADS + h] + mask[w * NN + nm];
    }
}

// ---------------------------------------------------------------------------
// Kernel 1/3: fp16 GEMM  C[m,n] = sum_k A[m,k]*B[n,k] + bias[n]
//   QKV_OUT=true: output fp16 in permuted [3][H][B_][49][32] layout,
//                 q columns pre-scaled by 32^-0.5.
//   QKV_OUT=false: fp32 row-major output (proj).
// ---------------------------------------------------------------------------
#define GBM 128
#define GBN 128
#define GBK 64
#define GSTG (GBM * GBK * 2)                  // 16384 bytes per tile
#define GEMM_SMEM_BYTES (4 * GSTG)            // 65536

template <bool QKV_OUT>
__global__ __launch_bounds__(256, 2)
void gemm_f16_pipe(const __half* __restrict__ A, const __half* __restrict__ B,
                   const float* __restrict__ bias, void* __restrict__ Cv,
                   int M, int N, int K) {
    extern __shared__ float dynsmem[];
    const uint32_t as_base = (uint32_t)__cvta_generic_to_shared(dynsmem);
    const uint32_t bs_base = as_base + 2 * GSTG;

    const int tid  = threadIdx.x;
    const int lane = tid & 31;
    const int warp = tid >> 5;
    const int wm   = warp >> 1;
    const int wn   = warp & 1;
    const int bm   = blockIdx.y * GBM;
    const int bn   = blockIdx.x * GBN;
    const int r4   = lane >> 2;
    const int c4   = lane & 3;

    const int lc4  = tid & 7;
    const int lrow = tid >> 3;
    const int pc4  = lc4 ^ (lrow & 7);

    const int l7       = lane & 7;
    const int a_half_m = (lane >> 3) & 1;
    const int a_half_k = lane >> 4;
    const int b_half_k = (lane >> 3) & 1;
    const int b_sel    = lane >> 4;

    int rA7[2]; uint32_t baseA[2];
    #pragma unroll
    for (int mt = 0; mt < 2; mt++) {
        int row = wm * 32 + mt * 16 + a_half_m * 8 + l7;
        rA7[mt]   = row & 7;
        baseA[mt] = (uint32_t)row * 128;
    }
    int rB7[4]; uint32_t baseB[4];
    #pragma unroll
    for (int j = 0; j < 4; j++) {
        int row = wn * 64 + (2 * j + b_sel) * 8 + l7;
        rB7[j]   = row & 7;
        baseB[j] = (uint32_t)row * 128;
    }

    const int kTiles = K / GBK;

    auto issue = [&](int ktf, int s) {
        #pragma unroll
        for (int i = 0; i < 4; i++) {
            int r = lrow + i * 32;
            cp_async16(as_base + (uint32_t)(s * GSTG + r * 128 + pc4 * 16),
                       A + (size_t)(bm + r) * K + ktf + lc4 * 8);
        }
        #pragma unroll
        for (int i = 0; i < 4; i++) {
            int r = lrow + i * 32;
            cp_async16(bs_base + (uint32_t)(s * GSTG + r * 128 + pc4 * 16),
                       B + (size_t)(bn + r) * K + ktf + lc4 * 8);
        }
        asm volatile("cp.async.commit_group;\n" ::: "memory");
    };

    float acc[2][8][4];
    #pragma unroll
    for (int mt = 0; mt < 2; mt++)
        #pragma unroll
        for (int nt = 0; nt < 8; nt++)
            #pragma unroll
            for (int i = 0; i < 4; i++) acc[mt][nt][i] = 0.f;

    issue(0, 0);

    for (int t = 0; t < kTiles; t++) {
        const int s = t & 1;
        if (t + 1 < kTiles) {
            issue((t + 1) * GBK, s ^ 1);
            asm volatile("cp.async.wait_group 1;\n" ::: "memory");
        } else {
            asm volatile("cp.async.wait_group 0;\n" ::: "memory");
        }
        __syncthreads();

        const uint32_t asb = as_base + (uint32_t)(s * GSTG);
        const uint32_t bsb = bs_base + (uint32_t)(s * GSTG);
        #pragma unroll
        for (int step = 0; step < 4; step++) {
            const int kk = step * 2;
            uint32_t af[2][4];
            uint32_t bf[8][2];
            #pragma unroll
            for (int mt = 0; mt < 2; mt++) {
                uint32_t addr = asb + baseA[mt] +
                                (uint32_t)(((kk + a_half_k) ^ rA7[mt]) << 4);
                ldsm_x4(af[mt][0], af[mt][1], af[mt][2], af[mt][3], addr);
            }
            #pragma unroll
            for (int j = 0; j < 4; j++) {
                uint32_t addr = bsb + baseB[j] +
                                (uint32_t)(((kk + b_half_k) ^ rB7[j]) << 4);
                ldsm_x4(bf[2 * j][0], bf[2 * j][1], bf[2 * j + 1][0], bf[2 * j + 1][1], addr);
            }
            #pragma unroll
            for (int mt = 0; mt < 2; mt++)
                #pragma unroll
                for (int nt = 0; nt < 8; nt++)
                    mma_f16_16x8x16(acc[mt][nt], af[mt], bf[nt]);
        }
        __syncthreads();
    }

    // epilogue
    const float qsc = 0.1767766952966369f;   // 32^-0.5
    #pragma unroll
    for (int mt = 0; mt < 2; mt++) {
        int row0 = bm + wm * 32 + mt * 16 + r4;
        if (QKV_OUT) {
            __half* C = (__half*)Cv;
            int t0 = row0, t1 = row0 + 8;
            int b0q = t0 / N_TOK, n0q = t0 - b0q * N_TOK;
            int b1q = t1 / N_TOK, n1q = t1 - b1q * N_TOK;
            #pragma unroll
            for (int nt = 0; nt < 8; nt++) {
                int col = bn + wn * 64 + nt * 8 + 2 * c4;
                int mtx = col / DIM;
                int rem = col - mtx * DIM;
                int hh  = rem >> 5;
                int dd  = rem & 31;
                float sc = (mtx == 0) ? qsc : 1.f;
                float bb0 = bias[col], bb1 = bias[col + 1];
                __half* base = C + (size_t)(mtx * H_HEADS + hh) * B_WIN * WHD + dd;
                *(__half2*)(base + ((size_t)b0q * N_TOK + n0q) * HD) =
                    __floats2half2_rn((acc[mt][nt][0] + bb0) * sc,
                                      (acc[mt][nt][1] + bb1) * sc);
                *(__half2*)(base + ((size_t)b1q * N_TOK + n1q) * HD) =
                    __floats2half2_rn((acc[mt][nt][2] + bb0) * sc,
                                      (acc[mt][nt][3] + bb1) * sc);
            }
        } else {
            float* C = (float*)Cv;
            #pragma unroll
            for (int nt = 0; nt < 8; nt++) {
                int col = bn + wn * 64 + nt * 8 + 2 * c4;
                float bb0 = bias[col], bb1 = bias[col + 1];
                *(float2*)(C + (size_t)row0 * N + col) =
                    make_float2(acc[mt][nt][0] + bb0, acc[mt][nt][1] + bb1);
                *(float2*)(C + (size_t)(row0 + 8) * N + col) =
                    make_float2(acc[mt][nt][2] + bb0, acc[mt][nt][3] + bb1);
            }
        }
    }
}

// ---------------------------------------------------------------------------
// Kernel 2: fused attention (fp16 mma + ldmatrix), 2 windows per CTA
//   grid (H=12, 64, 32), 256 threads.
//   SMEM per window (halves): q 49x40, k 49x40, v 64x40 (rows 49..63 = 0),
//   P 49x72 (cols 48..63 = 0). comb fp32 shared by both windows.
// ---------------------------------------------------------------------------
#define QSTRH 40
#define PSTRH 72
#define W_QK  (N_TOK * QSTRH)   // 1960
#define W_V   (64 * QSTRH)      // 2560
#define W_P   (N_TOK * PSTRH)   // 3528
#define HS_Q  0
#define HS_K  (2 * W_QK)        // 3920
#define HS_V  (4 * W_QK)        // 7840
#define HS_P  (4 * W_QK + 2 * W_V)   // 12960
#define HS_TOT (HS_P + 2 * W_P)      // 20016 halves
#define ATTN_SMEM_BYTES (HS_TOT * 2 + NN * 4)   // 49636

__global__ __launch_bounds__(256)
void attn_fused2_kernel() {
    extern __shared__ __align__(16) char smraw[];
    __half* hs = (__half*)smraw;
    float*  cb = (float*)(smraw + HS_TOT * 2);

    const int h    = blockIdx.x;
    const int tid  = threadIdx.x;
    const int wg   = tid >> 7;
    const int tl   = tid & 127;
    const int lane = tid & 31;
    const int warp = (tid >> 5) & 3;
    const int r4   = lane >> 2;
    const int c4   = lane & 3;
    const int l7   = lane & 7;
    const int g8   = (lane >> 3) & 1;
    const int g16  = lane >> 4;

    const int b = blockIdx.y + NW_MASK * (blockIdx.z + wg * 32);

    __half* qsw = hs + HS_Q + wg * W_QK;
    __half* ksw = hs + HS_K + wg * W_QK;
    __half* vsw = hs + HS_V + wg * W_V;
    __half* Psw = hs + HS_P + wg * W_P;

    // zero v rows 49..63 (cols 0..31) and P pad cols 48..63 (rows 0..48)
    for (int i = tl; i < 60; i += 128) {
        int r = 49 + (i >> 2);
        *(uint4*)&vsw[r * QSTRH + (i & 3) * 8] = make_uint4(0, 0, 0, 0);
    }
    for (int i = tl; i < 98; i += 128) {
        *(uint4*)&Psw[(i >> 1) * PSTRH + 48 + (i & 1) * 8] = make_uint4(0, 0, 0, 0);
    }

    // fill q,k,v: 3 x 196 contiguous 16B granules per window
    {
        const size_t blk = ((size_t)h * B_WIN + b) * WHD;
        const __half* qg = g_qkvh + blk;
        const __half* kg = g_qkvh + (size_t)H_HEADS * B_WIN * WHD + blk;
        const __half* vg = g_qkvh + 2 * (size_t)H_HEADS * B_WIN * WHD + blk;
        for (int idx = tl; idx < 588; idx += 128) {
            int mat = idx / 196;
            int g   = idx - mat * 196;
            const __half* src = (mat == 0) ? qg : (mat == 1) ? kg : vg;
            uint4 val = *(const uint4*)(src + g * 8);
            __half* dst = (mat == 0) ? qsw : (mat == 1) ? ksw : vsw;
            *(uint4*)&dst[(g >> 2) * QSTRH + (g & 3) * 8] = val;
        }
    }
    {
        const float* cbg = g_comb + (size_t)(h * NW_MASK + blockIdx.y) * NN;
        for (int i = tid; i < NN; i += 256) cb[i] = cbg[i];
    }
    __syncthreads();

    const uint32_t qsu = (uint32_t)__cvta_generic_to_shared(qsw);
    const uint32_t ksu = (uint32_t)__cvta_generic_to_shared(ksw);
    const uint32_t vsu = (uint32_t)__cvta_generic_to_shared(vsw);
    const uint32_t psu = (uint32_t)__cvta_generic_to_shared(Psw);

    const int am = warp * 16;

    // --- S = q' @ k^T (q pre-scaled); softmax fused in registers ---
    {
        float acc[7][4];
        #pragma unroll
        for (int nt = 0; nt < 7; nt++)
            #pragma unroll
            for (int i = 0; i < 4; i++) acc[nt][i] = 0.f;

        const uint32_t aBase = qsu + (uint32_t)min(am + g8 * 8 + l7, N_TOK - 1) * 80
                             + (uint32_t)g16 * 16;
        uint32_t bBase[3];
        #pragma unroll
        for (int j = 0; j < 3; j++)
            bBase[j] = ksu + (uint32_t)min((2 * j + g16) * 8 + l7, N_TOK - 1) * 80
                     + (uint32_t)g8 * 16;
        const uint32_t bBase6 = ksu + (uint32_t)(N_TOK - 1) * 80 + (uint32_t)g8 * 16;

        #pragma unroll
        for (int s = 0; s < 2; s++) {
            uint32_t af[4], bf[7][2];
            ldsm_x4(af[0], af[1], af[2], af[3], aBase + s * 32);
            #pragma unroll
            for (int j = 0; j < 3; j++)
                ldsm_x4(bf[2 * j][0], bf[2 * j][1], bf[2 * j + 1][0], bf[2 * j + 1][1],
                        bBase[j] + s * 32);
            ldsm_x2(bf[6][0], bf[6][1], bBase6 + s * 32);
            #pragma unroll
            for (int nt = 0; nt < 7; nt++)
                mma_f16_16x8x16(acc[nt], af, bf[nt]);
        }

        // fused softmax (fp32)
        const int n0  = am + r4;
        const int n1  = n0 + 8;
        const int cr0 = min(n0, N_TOK - 1) * N_TOK;
        const int cr1 = min(n1, N_TOK - 1) * N_TOK;
        float s0 = 0.f, s1 = 0.f;
        #pragma unroll
        for (int nt = 0; nt < 7; nt++) {
            int col0 = nt * 8 + 2 * c4;
            int col1 = col0 + 1;
            float e00 = (col0 < N_TOK) ? __expf(acc[nt][0] + cb[cr0 + col0]) : 0.f;
            float e01 = (col1 < N_TOK) ? __expf(acc[nt][1] + cb[cr0 + col1]) : 0.f;
            float e10 = (col0 < N_TOK) ? __expf(acc[nt][2] + cb[cr1 + col0]) : 0.f;
            float e11 = (col1 < N_TOK) ? __expf(acc[nt][3] + cb[cr1 + col1]) : 0.f;
            acc[nt][0] = e00; acc[nt][1] = e01; acc[nt][2] = e10; acc[nt][3] = e11;
            s0 += e00 + e01;
            s1 += e10 + e11;
        }
        s0 += __shfl_xor_sync(0xffffffffu, s0, 1);
        s0 += __shfl_xor_sync(0xffffffffu, s0, 2);
        s1 += __shfl_xor_sync(0xffffffffu, s1, 1);
        s1 += __shfl_xor_sync(0xffffffffu, s1, 2);
        float inv0 = __frcp_rn(s0);
        float inv1 = __frcp_rn(s1);

        #pragma unroll
        for (int nt = 0; nt < 7; nt++) {
            int col0 = nt * 8 + 2 * c4;
            int col1 = col0 + 1;
            if (col0 < N_TOK) {
                float p01 = (col1 < N_TOK) ? acc[nt][1] * inv0 : 0.f;
                float p11 = (col1 < N_TOK) ? acc[nt][3] * inv1 : 0.f;
                if (n0 < N_TOK)
                    *(__half2*)&Psw[n0 * PSTRH + col0] =
                        __floats2half2_rn(acc[nt][0] * inv0, p01);
                if (n1 < N_TOK)
                    *(__half2*)&Psw[n1 * PSTRH + col0] =
                        __floats2half2_rn(acc[nt][2] * inv1, p11);
            }
        }
    }
    __syncthreads();

    // --- O = P @ V: A via ldmatrix.x4, B via ldmatrix.x4.trans ---
    {
        float acc[4][4];
        #pragma unroll
        for (int nt = 0; nt < 4; nt++)
            #pragma unroll
            for (int i = 0; i < 4; i++) acc[nt][i] = 0.f;

        const uint32_t paBase = psu + (uint32_t)min(am + g8 * 8 + l7, N_TOK - 1) * 144
                              + (uint32_t)g16 * 16;
        const uint32_t vbBase = vsu + (uint32_t)(g8 * 8 + l7) * 80
                              + (uint32_t)g16 * 16;

        #pragma unroll
        for (int s = 0; s < 4; s++) {
            uint32_t af[4], bf[4][2];
            ldsm_x4(af[0], af[1], af[2], af[3], paBase + s * 32);
            ldsm_x4t(bf[0][0], bf[0][1], bf[1][0], bf[1][1], vbBase + s * 1280);
            ldsm_x4t(bf[2][0], bf[2][1], bf[3][0], bf[3][1], vbBase + s * 1280 + 32);
            #pragma unroll
            for (int nt = 0; nt < 4; nt++)
                mma_f16_16x8x16(acc[nt], af, bf[nt]);
        }
        __half* aob = g_aoh + (size_t)b * N_TOK * DIM + h * HD;
        const int n0 = am + r4, n1 = n0 + 8;
        #pragma unroll
        for (int nt = 0; nt < 4; nt++) {
            int col = nt * 8 + 2 * c4;
            if (n0 < N_TOK)
                *(__half2*)(aob + (size_t)n0 * DIM + col) =
                    __floats2half2_rn(acc[nt][0], acc[nt][1]);
            if (n1 < N_TOK)
                *(__half2*)(aob + (size_t)n1 * DIM + col) =
                    __floats2half2_rn(acc[nt][2], acc[nt][3]);
        }
    }
}

// ---------------------------------------------------------------------------
// launch
// ---------------------------------------------------------------------------
extern "C" void kernel_launch(void* const* d_in, const int* in_sizes, int n_in,
                              void* d_out, int out_size) {
    const float* x          = (const float*)d_in[0];
    const float* mask       = (const float*)d_in[1];
    const float* qkv_w      = (const float*)d_in[2];
    const float* qkv_b      = (const float*)d_in[3];
    const float* proj_w     = (const float*)d_in[4];
    const float* proj_b     = (const float*)d_in[5];
    const float* bias_table = (const float*)d_in[6];
    const int*   rel_index  = (const int*)d_in[7];
    float* out = (float*)d_out;

    void* p_qkvh = nullptr; void* p_aoh = nullptr;
    void* p_xh   = nullptr; void* p_wh  = nullptr;
    cudaGetSymbolAddress(&p_qkvh, g_qkvh);
    cudaGetSymbolAddress(&p_aoh,  g_aoh);
    cudaGetSymbolAddress(&p_xh,   g_xh);
    cudaGetSymbolAddress(&p_wh,   g_wh);
    __half* qkvh = (__half*)p_qkvh;
    __half* aoh  = (__half*)p_aoh;
    __half* xh   = (__half*)p_xh;
    __half* qkvw_h  = (__half*)p_wh;
    __half* projw_h = qkvw_h + 3 * DIM * DIM;

    cudaFuncSetAttribute(gemm_f16_pipe<true>,
                         cudaFuncAttributeMaxDynamicSharedMemorySize,
                         GEMM_SMEM_BYTES);
    cudaFuncSetAttribute(gemm_f16_pipe<false>,
                         cudaFuncAttributeMaxDynamicSharedMemorySize,
                         GEMM_SMEM_BYTES);
    cudaFuncSetAttribute(attn_fused2_kernel,
                         cudaFuncAttributeMaxDynamicSharedMemorySize,
                         ATTN_SMEM_BYTES);

    f32_to_f16_kernel<<<2048, 256>>>(x, xh, (T_TOT * DIM) / 4);
    f32_to_f16_kernel<<<256, 256>>>(qkv_w, qkvw_h, (3 * DIM * DIM) / 4);
    f32_to_f16_kernel<<<256, 256>>>(proj_w, projw_h, (DIM * DIM) / 4);
    {
        int n = H_HEADS * NW_MASK * NN;
        comb_kernel<<<(n + 255) / 256, 256>>>(bias_table, rel_index, mask);
    }
    // 1) QKV GEMM -> permuted fp16 [3][H][B_][49][32], q pre-scaled
    {
        dim3 grid((3 * DIM) / GBN, T_TOT / GBM);
        gemm_f16_pipe<true><<<grid, 256, GEMM_SMEM_BYTES>>>(
            xh, qkvw_h, qkv_b, qkvh, T_TOT, 3 * DIM, DIM);
    }
    // 2) fused attention: 2 windows per CTA, ldmatrix fragments
    {
        dim3 grid(H_HEADS, NW_MASK, B_WIN / NW_MASK / 2);
        attn_fused2_kernel<<<grid, 256, ATTN_SMEM_BYTES>>>();
    }
    // 3) proj GEMM: (T,384) @ (384,384)^T -> (T,384) fp32
    {
        dim3 grid(DIM / GBN, T_TOT / GBM);
        gemm_f16_pipe<false><<<grid, 256, GEMM_SMEM_BYTES>>>(
            aoh, projw_h, proj_b, out, T_TOT, DIM, DIM);
    }
}

// round 16
// speedup vs baseline: 1.9550x; 1.1185x over previous
#include <cuda_runtime.h>
#include <cuda_bf16.h>
#include <cuda_fp16.h>
#include <cstdint>
#include <cstddef>

// ---------------------------------------------------------------------------
// WindowAttention (Swin-style): B_=4096 windows, N=49, C=384, H=12, hd=32
// Round 16: attention CTA loops 16 windows (8 it x 2), comb loaded once,
//           q/k/v fill double-buffered via cp.async. Compute = R15.
// ---------------------------------------------------------------------------

#define B_WIN   4096
#define N_TOK   49
#define DIM     384
#define H_HEADS 12
#define HD      32
#define T_TOT   (B_WIN * N_TOK)      // 200704 tokens
#define NW_MASK 64
#define NN      (N_TOK * N_TOK)      // 2401
#define WHD     (N_TOK * HD)         // 1568 halves per (mtx,h,b)

__device__ __half g_qkvh[(size_t)3 * H_HEADS * B_WIN * WHD]; // permuted qkv
__device__ __half g_aoh [(size_t)T_TOT * DIM];      // (T, 384) fp16
__device__ __half g_xh  [(size_t)T_TOT * DIM];      // x, fp16
__device__ __half g_wh  [3 * DIM * DIM + DIM * DIM];// qkv_w | proj_w fp16
__device__ float  g_comb[(size_t)H_HEADS * NW_MASK * NN];  // bias+mask

// ---------------------------------------------------------------------------
// helpers
// ---------------------------------------------------------------------------
__device__ __forceinline__ void mma_f16_16x8x16(float d[4], const uint32_t a[4],
                                                const uint32_t b[2]) {
    asm volatile(
        "mma.sync.aligned.m16n8k16.row.col.f32.f16.f16.f32 "
        "{%0,%1,%2,%3}, {%4,%5,%6,%7}, {%8,%9}, {%0,%1,%2,%3};\n"
        : "+f"(d[0]), "+f"(d[1]), "+f"(d[2]), "+f"(d[3])
        : "r"(a[0]), "r"(a[1]), "r"(a[2]), "r"(a[3]), "r"(b[0]), "r"(b[1]));
}

__device__ __forceinline__ void ldsm_x4(uint32_t& r0, uint32_t& r1,
                                        uint32_t& r2, uint32_t& r3, uint32_t addr) {
    asm volatile("ldmatrix.sync.aligned.m8n8.x4.shared.b16 {%0,%1,%2,%3}, [%4];\n"
                 : "=r"(r0), "=r"(r1), "=r"(r2), "=r"(r3) : "r"(addr));
}

__device__ __forceinline__ void ldsm_x4t(uint32_t& r0, uint32_t& r1,
                                         uint32_t& r2, uint32_t& r3, uint32_t addr) {
    asm volatile("ldmatrix.sync.aligned.m8n8.x4.trans.shared.b16 {%0,%1,%2,%3}, [%4];\n"
                 : "=r"(r0), "=r"(r1), "=r"(r2), "=r"(r3) : "r"(addr));
}

__device__ __forceinline__ void ldsm_x2(uint32_t& r0, uint32_t& r1, uint32_t addr) {
    asm volatile("ldmatrix.sync.aligned.m8n8.x2.shared.b16 {%0,%1}, [%2];\n"
                 : "=r"(r0), "=r"(r1) : "r"(addr));
}

__device__ __forceinline__ void cp_async16(uint32_t smem_addr, const void* gptr) {
    asm volatile("cp.async.cg.shared.global [%0], [%1], 16;\n"
                 :: "r"(smem_addr), "l"(gptr) : "memory");
}

// ---------------------------------------------------------------------------
// Kernel R: convert fp32 -> fp16 (RN)
// ---------------------------------------------------------------------------
__global__ void f32_to_f16_kernel(const float* __restrict__ src,
                                  __half* __restrict__ dst, int n4) {
    int i = blockIdx.x * blockDim.x + threadIdx.x;
    int stride = gridDim.x * blockDim.x;
    for (; i < n4; i += stride) {
        float4 v = ((const float4*)src)[i];
        __half2 h01 = __floats2half2_rn(v.x, v.y);
        __half2 h23 = __floats2half2_rn(v.z, v.w);
        uint2 o;
        o.x = *(uint32_t*)&h01;
        o.y = *(uint32_t*)&h23;
        ((uint2*)dst)[i] = o;
    }
}

// ---------------------------------------------------------------------------
// Kernel 0: comb[h][w][n][m] = bias_table[rel_index[n,m]][h] + mask[w][n][m]
// ---------------------------------------------------------------------------
__global__ void comb_kernel(const float* __restrict__ bias_table,
                            const int* __restrict__ rel_index,
                            const float* __restrict__ mask) {
    int idx = blockIdx.x * blockDim.x + threadIdx.x;
    if (idx < H_HEADS * NW_MASK * NN) {
        int h   = idx / (NW_MASK * NN);
        int rem = idx - h * (NW_MASK * NN);
        int w   = rem / NN;
        int nm  = rem - w * NN;
        g_comb[idx] = bias_table[rel_index[nm] * H_HEADS + h] + mask[w * NN + nm];
    }
}

// ---------------------------------------------------------------------------
// Kernel 1/3: fp16 GEMM (unchanged from R15)
// ---------------------------------------------------------------------------
#define GBM 128
#define GBN 128
#define GBK 64
#define GSTG (GBM * GBK * 2)                  // 16384 bytes per tile
#define GEMM_SMEM_BYTES (4 * GSTG)            // 65536

template <bool QKV_OUT>
__global__ __launch_bounds__(256, 2)
void gemm_f16_pipe(const __half* __restrict__ A, const __half* __restrict__ B,
                   const float* __restrict__ bias, void* __restrict__ Cv,
                   int M, int N, int K) {
    extern __shared__ float dynsmem[];
    const uint32_t as_base = (uint32_t)__cvta_generic_to_shared(dynsmem);
    const uint32_t bs_base = as_base + 2 * GSTG;

    const int tid  = threadIdx.x;
    const int lane = tid & 31;
    const int warp = tid >> 5;
    const int wm   = warp >> 1;
    const int wn   = warp & 1;
    const int bm   = blockIdx.y * GBM;
    const int bn   = blockIdx.x * GBN;
    const int r4   = lane >> 2;
    const int c4   = lane & 3;

    const int lc4  = tid & 7;
    const int lrow = tid >> 3;
    const int pc4  = lc4 ^ (lrow & 7);

    const int l7       = lane & 7;
    const int a_half_m = (lane >> 3) & 1;
    const int a_half_k = lane >> 4;
    const int b_half_k = (lane >> 3) & 1;
    const int b_sel    = lane >> 4;

    int rA7[2]; uint32_t baseA[2];
    #pragma unroll
    for (int mt = 0; mt < 2; mt++) {
        int row = wm * 32 + mt * 16 + a_half_m * 8 + l7;
        rA7[mt]   = row & 7;
        baseA[mt] = (uint32_t)row * 128;
    }
    int rB7[4]; uint32_t baseB[4];
    #pragma unroll
    for (int j = 0; j < 4; j++) {
        int row = wn * 64 + (2 * j + b_sel) * 8 + l7;
        rB7[j]   = row & 7;
        baseB[j] = (uint32_t)row * 128;
    }

    const int kTiles = K / GBK;

    auto issue = [&](int ktf, int s) {
        #pragma unroll
        for (int i = 0; i < 4; i++) {
            int r = lrow + i * 32;
            cp_async16(as_base + (uint32_t)(s * GSTG + r * 128 + pc4 * 16),
                       A + (size_t)(bm + r) * K + ktf + lc4 * 8);
        }
        #pragma unroll
        for (int i = 0; i < 4; i++) {
            int r = lrow + i * 32;
            cp_async16(bs_base + (uint32_t)(s * GSTG + r * 128 + pc4 * 16),
                       B + (size_t)(bn + r) * K + ktf + lc4 * 8);
        }
        asm volatile("cp.async.commit_group;\n" ::: "memory");
    };

    float acc[2][8][4];
    #pragma unroll
    for (int mt = 0; mt < 2; mt++)
        #pragma unroll
        for (int nt = 0; nt < 8; nt++)
            #pragma unroll
            for (int i = 0; i < 4; i++) acc[mt][nt][i] = 0.f;

    issue(0, 0);

    for (int t = 0; t < kTiles; t++) {
        const int s = t & 1;
        if (t + 1 < kTiles) {
            issue((t + 1) * GBK, s ^ 1);
            asm volatile("cp.async.wait_group 1;\n" ::: "memory");
        } else {
            asm volatile("cp.async.wait_group 0;\n" ::: "memory");
        }
        __syncthreads();

        const uint32_t asb = as_base + (uint32_t)(s * GSTG);
        const uint32_t bsb = bs_base + (uint32_t)(s * GSTG);
        #pragma unroll
        for (int step = 0; step < 4; step++) {
            const int kk = step * 2;
            uint32_t af[2][4];
            uint32_t bf[8][2];
            #pragma unroll
            for (int mt = 0; mt < 2; mt++) {
                uint32_t addr = asb + baseA[mt] +
                                (uint32_t)(((kk + a_half_k) ^ rA7[mt]) << 4);
                ldsm_x4(af[mt][0], af[mt][1], af[mt][2], af[mt][3], addr);
            }
            #pragma unroll
            for (int j = 0; j < 4; j++) {
                uint32_t addr = bsb + baseB[j] +
                                (uint32_t)(((kk + b_half_k) ^ rB7[j]) << 4);
                ldsm_x4(bf[2 * j][0], bf[2 * j][1], bf[2 * j + 1][0], bf[2 * j + 1][1], addr);
            }
            #pragma unroll
            for (int mt = 0; mt < 2; mt++)
                #pragma unroll
                for (int nt = 0; nt < 8; nt++)
                    mma_f16_16x8x16(acc[mt][nt], af[mt], bf[nt]);
        }
        __syncthreads();
    }

    // epilogue
    const float qsc = 0.1767766952966369f;   // 32^-0.5
    #pragma unroll
    for (int mt = 0; mt < 2; mt++) {
        int row0 = bm + wm * 32 + mt * 16 + r4;
        if (QKV_OUT) {
            __half* C = (__half*)Cv;
            int t0 = row0, t1 = row0 + 8;
            int b0q = t0 / N_TOK, n0q = t0 - b0q * N_TOK;
            int b1q = t1 / N_TOK, n1q = t1 - b1q * N_TOK;
            #pragma unroll
            for (int nt = 0; nt < 8; nt++) {
                int col = bn + wn * 64 + nt * 8 + 2 * c4;
                int mtx = col / DIM;
                int rem = col - mtx * DIM;
                int hh  = rem >> 5;
                int dd  = rem & 31;
                float sc = (mtx == 0) ? qsc : 1.f;
                float bb0 = bias[col], bb1 = bias[col + 1];
                __half* base = C + (size_t)(mtx * H_HEADS + hh) * B_WIN * WHD + dd;
                *(__half2*)(base + ((size_t)b0q * N_TOK + n0q) * HD) =
                    __floats2half2_rn((acc[mt][nt][0] + bb0) * sc,
                                      (acc[mt][nt][1] + bb1) * sc);
                *(__half2*)(base + ((size_t)b1q * N_TOK + n1q) * HD) =
                    __floats2half2_rn((acc[mt][nt][2] + bb0) * sc,
                                      (acc[mt][nt][3] + bb1) * sc);
            }
        } else {
            float* C = (float*)Cv;
            #pragma unroll
            for (int nt = 0; nt < 8; nt++) {
                int col = bn + wn * 64 + nt * 8 + 2 * c4;
                float bb0 = bias[col], bb1 = bias[col + 1];
                *(float2*)(C + (size_t)row0 * N + col) =
                    make_float2(acc[mt][nt][0] + bb0, acc[mt][nt][1] + bb1);
                *(float2*)(C + (size_t)(row0 + 8) * N + col) =
                    make_float2(acc[mt][nt][2] + bb0, acc[mt][nt][3] + bb1);
            }
        }
    }
}

// ---------------------------------------------------------------------------
// Kernel 2: fused attention, looped windows with cp.async double buffer
//   grid (H=12, 64, 4), 256 threads; each CTA: 8 iterations x 2 windows,
//   all sharing one comb tile. Compute body identical to R15.
// ---------------------------------------------------------------------------
#define QSTRH 40
#define PSTRH 72
#define W_QK  (N_TOK * QSTRH)       // 1960 halves
#define W_V   (64 * QSTRH)          // 2560 halves (rows 49..63 zero)
#define W_BUF (2 * W_QK + W_V)      // 6480 halves per window buffer
#define HS_BUFS (4 * W_BUF)         // 2 stages x 2 windows = 25920
#define W_P   (N_TOK * PSTRH)       // 3528
#define HS_P  HS_BUFS
#define HS_TOT (HS_BUFS + 2 * W_P)  // 32976 halves
#define ATTN_SMEM_BYTES (HS_TOT * 2 + NN * 4)   // 75556
#define AITERS 8

__global__ __launch_bounds__(256)
void attn_loop_kernel() {
    extern __shared__ __align__(16) char smraw[];
    __half* hs = (__half*)smraw;
    float*  cb = (float*)(smraw + HS_TOT * 2);
    const uint32_t hs_u = (uint32_t)__cvta_generic_to_shared(hs);

    const int h    = blockIdx.x;
    const int w    = blockIdx.y;
    const int z    = blockIdx.z;
    const int tid  = threadIdx.x;
    const int wg   = tid >> 7;
    const int lane = tid & 31;
    const int warp = (tid >> 5) & 3;
    const int r4   = lane >> 2;
    const int c4   = lane & 3;
    const int l7   = lane & 7;
    const int g8   = (lane >> 3) & 1;
    const int g16  = lane >> 4;

    // zero v pad rows (49..63) in all 4 buffers, and P pad cols (48..63)
    for (int i = tid; i < 4 * 60; i += 256) {
        int buf = i / 60, r = i % 60;
        __half* v = hs + buf * W_BUF + 2 * W_QK;
        *(uint4*)&v[(49 + (r >> 2)) * QSTRH + (r & 3) * 8] = make_uint4(0, 0, 0, 0);
    }
    for (int i = tid; i < 2 * 98; i += 256) {
        int ww = i / 98, r = i % 98;
        __half* P = hs + HS_P + ww * W_P;
        *(uint4*)&P[(r >> 1) * PSTRH + 48 + (r & 1) * 8] = make_uint4(0, 0, 0, 0);
    }
    // comb tile (shared by all 16 windows of this CTA)
    {
        const float* cbg = g_comb + (size_t)(h * NW_MASK + w) * NN;
        for (int i = tid; i < NN; i += 256) cb[i] = cbg[i];
    }

    // fill: both windows of iteration it into stage s (1176 granules)
    auto issue = [&](int it, int s) {
        #pragma unroll 5
        for (int idx = tid; idx < 1176; idx += 256) {
            int wslot = idx / 588;
            int r     = idx - wslot * 588;
            int mat   = r / 196;
            int g     = r - mat * 196;
            int bw    = w + NW_MASK * (z * (2 * AITERS) + 2 * it + wslot);
            const __half* src = g_qkvh + (size_t)mat * H_HEADS * B_WIN * WHD
                              + ((size_t)h * B_WIN + bw) * WHD + g * 8;
            uint32_t dst = hs_u + (uint32_t)((s * 2 + wslot) * W_BUF + mat * W_QK) * 2
                         + (uint32_t)((g >> 2) * QSTRH + (g & 3) * 8) * 2;
            // mat==2 (v) also lands at 2*W_QK since offsets q:0,k:W_QK,v:2*W_QK
            cp_async16(dst, src);
        }
        asm volatile("cp.async.commit_group;\n" ::: "memory");
    };

    issue(0, 0);

    const int am = warp * 16;

    for (int it = 0; it < AITERS; it++) {
        const int s = it & 1;
        if (it + 1 < AITERS) {
            issue(it + 1, s ^ 1);
            asm volatile("cp.async.wait_group 1;\n" ::: "memory");
        } else {
            asm volatile("cp.async.wait_group 0;\n" ::: "memory");
        }
        __syncthreads();

        const int b = w + NW_MASK * (z * (2 * AITERS) + 2 * it + wg);
        __half* qsw = hs + (s * 2 + wg) * W_BUF;
        __half* ksw = qsw + W_QK;
        __half* vsw = qsw + 2 * W_QK;
        __half* Psw = hs + HS_P + wg * W_P;
        const uint32_t qsu = (uint32_t)__cvta_generic_to_shared(qsw);
        const uint32_t ksu = (uint32_t)__cvta_generic_to_shared(ksw);
        const uint32_t vsu = (uint32_t)__cvta_generic_to_shared(vsw);
        const uint32_t psu = (uint32_t)__cvta_generic_to_shared(Psw);

        // --- S = q' @ k^T; fused softmax ---
        {
            float acc[7][4];
            #pragma unroll
            for (int nt = 0; nt < 7; nt++)
                #pragma unroll
                for (int i = 0; i < 4; i++) acc[nt][i] = 0.f;

            const uint32_t aBase = qsu + (uint32_t)min(am + g8 * 8 + l7, N_TOK - 1) * 80
                                 + (uint32_t)g16 * 16;
            uint32_t bBase[3];
            #pragma unroll
            for (int j = 0; j < 3; j++)
                bBase[j] = ksu + (uint32_t)min((2 * j + g16) * 8 + l7, N_TOK - 1) * 80
                         + (uint32_t)g8 * 16;
            const uint32_t bBase6 = ksu + (uint32_t)(N_TOK - 1) * 80 + (uint32_t)g8 * 16;

            #pragma unroll
            for (int sk = 0; sk < 2; sk++) {
                uint32_t af[4], bf[7][2];
                ldsm_x4(af[0], af[1], af[2], af[3], aBase + sk * 32);
                #pragma unroll
                for (int j = 0; j < 3; j++)
                    ldsm_x4(bf[2 * j][0], bf[2 * j][1], bf[2 * j + 1][0], bf[2 * j + 1][1],
                            bBase[j] + sk * 32);
                ldsm_x2(bf[6][0], bf[6][1], bBase6 + sk * 32);
                #pragma unroll
                for (int nt = 0; nt < 7; nt++)
                    mma_f16_16x8x16(acc[nt], af, bf[nt]);
            }

            const int n0  = am + r4;
            const int n1  = n0 + 8;
            const int cr0 = min(n0, N_TOK - 1) * N_TOK;
            const int cr1 = min(n1, N_TOK - 1) * N_TOK;
            float s0 = 0.f, s1 = 0.f;
            #pragma unroll
            for (int nt = 0; nt < 7; nt++) {
                int col0 = nt * 8 + 2 * c4;
                int col1 = col0 + 1;
                float e00 = (col0 < N_TOK) ? __expf(acc[nt][0] + cb[cr0 + col0]) : 0.f;
                float e01 = (col1 < N_TOK) ? __expf(acc[nt][1] + cb[cr0 + col1]) : 0.f;
                float e10 = (col0 < N_TOK) ? __expf(acc[nt][2] + cb[cr1 + col0]) : 0.f;
                float e11 = (col1 < N_TOK) ? __expf(acc[nt][3] + cb[cr1 + col1]) : 0.f;
                acc[nt][0] = e00; acc[nt][1] = e01; acc[nt][2] = e10; acc[nt][3] = e11;
                s0 += e00 + e01;
                s1 += e10 + e11;
            }
            s0 += __shfl_xor_sync(0xffffffffu, s0, 1);
            s0 += __shfl_xor_sync(0xffffffffu, s0, 2);
            s1 += __shfl_xor_sync(0xffffffffu, s1, 1);
            s1 += __shfl_xor_sync(0xffffffffu, s1, 2);
            float inv0 = __frcp_rn(s0);
            float inv1 = __frcp_rn(s1);

            #pragma unroll
            for (int nt = 0; nt < 7; nt++) {
                int col0 = nt * 8 + 2 * c4;
                int col1 = col0 + 1;
                if (col0 < N_TOK) {
                    float p01 = (col1 < N_TOK) ? acc[nt][1] * inv0 : 0.f;
                    float p11 = (col1 < N_TOK) ? acc[nt][3] * inv1 : 0.f;
                    if (n0 < N_TOK)
                        *(__half2*)&Psw[n0 * PSTRH + col0] =
                            __floats2half2_rn(acc[nt][0] * inv0, p01);
                    if (n1 < N_TOK)
                        *(__half2*)&Psw[n1 * PSTRH + col0] =
                            __floats2half2_rn(acc[nt][2] * inv1, p11);
                }
            }
        }
        __syncthreads();

        // --- O = P @ V ---
        {
            float acc[4][4];
            #pragma unroll
            for (int nt = 0; nt < 4; nt++)
                #pragma unroll
                for (int i = 0; i < 4; i++) acc[nt][i] = 0.f;

            const uint32_t paBase = psu + (uint32_t)min(am + g8 * 8 + l7, N_TOK - 1) * 144
                                  + (uint32_t)g16 * 16;
            const uint32_t vbBase = vsu + (uint32_t)(g8 * 8 + l7) * 80
                                  + (uint32_t)g16 * 16;

            #pragma unroll
            for (int sk = 0; sk < 4; sk++) {
                uint32_t af[4], bf[4][2];
                ldsm_x4(af[0], af[1], af[2], af[3], paBase + sk * 32);
                ldsm_x4t(bf[0][0], bf[0][1], bf[1][0], bf[1][1], vbBase + sk * 1280);
                ldsm_x4t(bf[2][0], bf[2][1], bf[3][0], bf[3][1], vbBase + sk * 1280 + 32);
                #pragma unroll
                for (int nt = 0; nt < 4; nt++)
                    mma_f16_16x8x16(acc[nt], af, bf[nt]);
            }
            __half* aob = g_aoh + (size_t)b * N_TOK * DIM + h * HD;
            const int n0 = am + r4, n1 = n0 + 8;
            #pragma unroll
            for (int nt = 0; nt < 4; nt++) {
                int col = nt * 8 + 2 * c4;
                if (n0 < N_TOK)
                    *(__half2*)(aob + (size_t)n0 * DIM + col) =
                        __floats2half2_rn(acc[nt][0], acc[nt][1]);
                if (n1 < N_TOK)
                    *(__half2*)(aob + (size_t)n1 * DIM + col) =
                        __floats2half2_rn(acc[nt][2], acc[nt][3]);
            }
        }
        __syncthreads();
    }
}

// ---------------------------------------------------------------------------
// launch
// ---------------------------------------------------------------------------
extern "C" void kernel_launch(void* const* d_in, const int* in_sizes, int n_in,
                              void* d_out, int out_size) {
    const float* x          = (const float*)d_in[0];
    const float* mask       = (const float*)d_in[1];
    const float* qkv_w      = (const float*)d_in[2];
    const float* qkv_b      = (const float*)d_in[3];
    const float* proj_w     = (const float*)d_in[4];
    const float* proj_b     = (const float*)d_in[5];
    const float* bias_table = (const float*)d_in[6];
    const int*   rel_index  = (const int*)d_in[7];
    float* out = (float*)d_out;

    void* p_qkvh = nullptr; void* p_aoh = nullptr;
    void* p_xh   = nullptr; void* p_wh  = nullptr;
    cudaGetSymbolAddress(&p_qkvh, g_qkvh);
    cudaGetSymbolAddress(&p_aoh,  g_aoh);
    cudaGetSymbolAddress(&p_xh,   g_xh);
    cudaGetSymbolAddress(&p_wh,   g_wh);
    __half* qkvh = (__half*)p_qkvh;
    __half* aoh  = (__half*)p_aoh;
    __half* xh   = (__half*)p_xh;
    __half* qkvw_h  = (__half*)p_wh;
    __half* projw_h = qkvw_h + 3 * DIM * DIM;

    cudaFuncSetAttribute(gemm_f16_pipe<true>,
                         cudaFuncAttributeMaxDynamicSharedMemorySize,
                         GEMM_SMEM_BYTES);
    cudaFuncSetAttribute(gemm_f16_pipe<false>,
                         cudaFuncAttributeMaxDynamicSharedMemorySize,
                         GEMM_SMEM_BYTES);
    cudaFuncSetAttribute(attn_loop_kernel,
                         cudaFuncAttributeMaxDynamicSharedMemorySize,
                         ATTN_SMEM_BYTES);

    f32_to_f16_kernel<<<2048, 256>>>(x, xh, (T_TOT * DIM) / 4);
    f32_to_f16_kernel<<<256, 256>>>(qkv_w, qkvw_h, (3 * DIM * DIM) / 4);
    f32_to_f16_kernel<<<256, 256>>>(proj_w, projw_h, (DIM * DIM) / 4);
    {
        int n = H_HEADS * NW_MASK * NN;
        comb_kernel<<<(n + 255) / 256, 256>>>(bias_table, rel_index, mask);
    }
    // 1) QKV GEMM -> permuted fp16 [3][H][B_][49][32], q pre-scaled
    {
        dim3 grid((3 * DIM) / GBN, T_TOT / GBM);
        gemm_f16_pipe<true><<<grid, 256, GEMM_SMEM_BYTES>>>(
            xh, qkvw_h, qkv_b, qkvh, T_TOT, 3 * DIM, DIM);
    }
    // 2) fused attention: looped windows, double-buffered fill
    {
        dim3 grid(H_HEADS, NW_MASK, B_WIN / NW_MASK / (2 * AITERS));
        attn_loop_kernel<<<grid, 256, ATTN_SMEM_BYTES>>>();
    }
    // 3) proj GEMM: (T,384) @ (384,384)^T -> (T,384) fp32
    {
        dim3 grid(DIM / GBN, T_TOT / GBM);
        gemm_f16_pipe<false><<<grid, 256, GEMM_SMEM_BYTES>>>(
            aoh, projw_h, proj_b, out, T_TOT, DIM, DIM);
    }
}